// round 2
// baseline (speedup 1.0000x reference)
#include <cuda_runtime.h>
#include <cstdint>

typedef unsigned long long ull;

#define BB    2048
#define DIMD  200
#define NENT  100000
#define WELEM 8000000
#define BNEPS 1e-5f

#define OFF_PRED 0LL
#define OFF_REG  204800000LL
#define OFF_T    204800005LL

// ---------------- device scratch (no allocations allowed) ----------------
__device__ float g_lhs  [BB*DIMD];
__device__ float g_relt [BB*DIMD];
__device__ float g_lhsn [BB*DIMD];
__device__ float g_colp [128*2*DIMD];
__device__ float g_s4p  [128*3];
__device__ float g_scale0[DIMD];
__device__ float g_shift0[DIMD];
__device__ float g_regsums[4];
__device__ float g_n4p  [512*2];
__device__ float g_hp   [8*BB*DIMD];
__device__ float g_h    [BB*DIMD];
__device__ float g_hn   [BB*DIMD];
__device__ float g_scale1[DIMD];
__device__ float g_shift1[DIMD];

// ---------------- packed f32x2 helpers (FFMA2 path) ----------------
__device__ __forceinline__ void fma2(ull& d, ull a, ull b) {
    asm("fma.rn.f32x2 %0, %1, %2, %0;" : "+l"(d) : "l"(a), "l"(b));
}
__device__ __forceinline__ ull pack2(float x) {
    ull r;
    asm("mov.b64 %0, {%1, %1};" : "=l"(r) : "r"(__float_as_uint(x)));
    return r;
}

__device__ __forceinline__ float blockReduce256(float v, float* red) {
    int t = threadIdx.x;
    red[t] = v; __syncthreads();
#pragma unroll
    for (int s = 128; s > 0; s >>= 1) {
        if (t < s) red[t] += red[t + s];
        __syncthreads();
    }
    float r = red[0]; __syncthreads();
    return r;
}

// ---------------- K1: gather + BN0 column partials + norm4 partials ----------------
__global__ void k_gather(const int* __restrict__ x,
                         const float* __restrict__ E,
                         const float* __restrict__ R,
                         const float* __restrict__ RnT,
                         const float* __restrict__ T)
{
    __shared__ float red[256];
    int t = threadIdx.x;
    int d = t;
    float cs = 0.f, cq = 0.f, s_rt = 0.f, s_rn = 0.f, s_rh = 0.f;
    if (d < DIMD) {
#pragma unroll 4
        for (int i = 0; i < 16; i++) {
            int b = blockIdx.x * 16 + i;
            int i0 = x[b*4+0];
            int i1 = x[b*4+1];
            int i2 = x[b*4+2];
            int i3 = x[b*4+3];
            float l  = E[(size_t)i0*DIMD + d];
            float rt = R[(size_t)i1*DIMD + d] * T[(size_t)i3*DIMD + d];
            float rn = RnT[(size_t)i1*DIMD + d];
            float rh = E[(size_t)i2*DIMD + d];
            g_lhs [b*DIMD + d] = l;
            g_relt[b*DIMD + d] = rt;
            cs += l; cq += l*l;
            float a = rt*rt; s_rt += a*a;
            float bq = rn*rn; s_rn += bq*bq;
            float cc = rh*rh; s_rh += cc*cc;
        }
        g_colp[blockIdx.x*2*DIMD + d]        = cs;
        g_colp[blockIdx.x*2*DIMD + DIMD + d] = cq;
    }
    float r0 = blockReduce256(s_rt, red);
    float r1 = blockReduce256(s_rn, red);
    float r2 = blockReduce256(s_rh, red);
    if (t == 0) {
        g_s4p[blockIdx.x*3 + 0] = r0;
        g_s4p[blockIdx.x*3 + 1] = r1;
        g_s4p[blockIdx.x*3 + 2] = r2;
    }
}

// ---------------- K2: finalize BN0 stats + reg sums 1..3 ----------------
__global__ void k_stats0(const float* __restrict__ gamma0, const float* __restrict__ beta0)
{
    int t = threadIdx.x;
    if (t < DIMD) {
        float s = 0.f, sq = 0.f;
        for (int k = 0; k < 128; k++) {
            s  += g_colp[k*2*DIMD + t];
            sq += g_colp[k*2*DIMD + DIMD + t];
        }
        float mu  = s  * (1.f/2048.f);
        float var = sq * (1.f/2048.f) - mu*mu;
        float rs  = rsqrtf(var + BNEPS);
        float sc  = rs * gamma0[t];
        g_scale0[t] = sc;
        g_shift0[t] = beta0[t] - mu*sc;
    } else if (t < DIMD + 3) {
        int j = t - DIMD;
        float s = 0.f;
        for (int k = 0; k < 128; k++) s += g_s4p[k*3 + j];
        g_regsums[j + 1] = s;
    }
}

// ---------------- K3: norm4(W) + norm4(lhs_n); also materializes lhs_n ----------------
__global__ void k_norm4(const float* __restrict__ W)
{
    __shared__ float red[256];
    int t = threadIdx.x;
    float pw = 0.f, pl = 0.f;
    const int TOT = WELEM + BB*DIMD;
    for (int idx = blockIdx.x*256 + t; idx < TOT; idx += 512*256) {
        if (idx < WELEM) {
            float v = W[idx]; float v2 = v*v; pw += v2*v2;
        } else {
            int i = idx - WELEM;
            int d = i % DIMD;
            float v = g_lhs[i] * g_scale0[d] + g_shift0[d];
            g_lhsn[i] = v;
            float v2 = v*v; pl += v2*v2;
        }
    }
    float rl = blockReduce256(pl, red);
    float rw = blockReduce256(pw, red);
    if (t == 0) {
        g_n4p[blockIdx.x*2 + 0] = rl;
        g_n4p[blockIdx.x*2 + 1] = rw;
    }
}

// ---------------- K4: write reg[5] to output ----------------
__global__ void k_finreg(float* __restrict__ out)
{
    __shared__ float red[256];
    int t = threadIdx.x;
    float a = 0.f, b = 0.f;
    for (int i = t; i < 512; i += 256) { a += g_n4p[2*i]; b += g_n4p[2*i + 1]; }
    float sl = blockReduce256(a, red);
    float sw = blockReduce256(b, red);
    if (t == 0) {
        out[OFF_REG + 0] = powf(sl,            0.25f);
        out[OFF_REG + 1] = powf(g_regsums[1],  0.25f);
        out[OFF_REG + 2] = powf(g_regsums[2],  0.25f);
        out[OFF_REG + 3] = powf(g_regsums[3],  0.25f);
        out[OFF_REG + 4] = powf(sw,            0.25f);
    }
}

// ---------------- K5: GEMM-A (bilinear, k-split partials) ----------------
// h[b,e] = sum_kk sum_dd relt[b,kk]*lhsn[b,dd]*W[kk,dd,e]
// block: 64 batches x 200 e, kk range of 25. 200 threads, thread tile 8b x 8e.
#define SMEM_A 110080
__global__ void __launch_bounds__(200, 2) k_gemmA(const float* __restrict__ W)
{
    extern __shared__ float smA[];
    float* u_sm  = smA;            // 64 x 25
    float* v_sm  = smA + 1600;     // 64 x 200
    float* w_sm  = smA + 14400;    // 40 x 200
    ull*   c_dup = (ull*)(smA + 22400); // 40 x 64 packed (v,v)

    int t   = threadIdx.x;
    int b0  = blockIdx.x * 64;
    int kk0 = blockIdx.y * 25;

    for (int i = t; i < 1600; i += 200) {
        int b = i / 25, j = i % 25;
        u_sm[i] = g_relt[(b0 + b)*DIMD + kk0 + j];
    }
    for (int i = t; i < 12800; i += 200) {
        v_sm[i] = g_lhsn[(b0 + (i/200))*DIMD + (i%200)];
    }
    __syncthreads();

    int et = t % 25, bt = t / 25;
    int eb = et * 8, bb = bt * 8;

    ull acc[8][4];
#pragma unroll
    for (int i = 0; i < 8; i++)
#pragma unroll
        for (int j = 0; j < 4; j++) acc[i][j] = 0ULL;

    for (int kk = 0; kk < 25; kk++) {
        const float* Wk = W + (size_t)(kk0 + kk) * 40000;
        for (int c = 0; c < 5; c++) {
            int dd0 = c * 40;
            __syncthreads();
            {   // load W chunk 40x200 (contiguous)
                const float4* Wg = (const float4*)(Wk + dd0*200);
                float4* wd = (float4*)w_sm;
                for (int i = t; i < 2000; i += 200) wd[i] = Wg[i];
            }
            for (int i = t; i < 2560; i += 200) {
                int dd = i / 64, b = i % 64;
                c_dup[i] = pack2(u_sm[b*25 + kk] * v_sm[b*200 + dd0 + dd]);
            }
            __syncthreads();
#pragma unroll 2
            for (int dd = 0; dd < 40; dd++) {
                const ull*   cr = c_dup + dd*64 + bb;
                const float* wr = w_sm  + dd*200 + eb;
                ulonglong2 a01 = *(const ulonglong2*)(cr);
                ulonglong2 a23 = *(const ulonglong2*)(cr + 2);
                ulonglong2 a45 = *(const ulonglong2*)(cr + 4);
                ulonglong2 a67 = *(const ulonglong2*)(cr + 6);
                ulonglong2 w01 = *(const ulonglong2*)(wr);
                ulonglong2 w23 = *(const ulonglong2*)(wr + 4);
                ull a[8] = {a01.x, a01.y, a23.x, a23.y, a45.x, a45.y, a67.x, a67.y};
                ull w[4] = {w01.x, w01.y, w23.x, w23.y};
#pragma unroll
                for (int i = 0; i < 8; i++)
#pragma unroll
                    for (int j = 0; j < 4; j++) fma2(acc[i][j], a[i], w[j]);
            }
        }
    }

    float* base = g_hp + (size_t)blockIdx.y * (BB*DIMD);
#pragma unroll
    for (int i = 0; i < 8; i++) {
        ull* q = (ull*)(base + (size_t)(b0 + bb + i)*DIMD + eb);
        q[0] = acc[i][0]; q[1] = acc[i][1]; q[2] = acc[i][2]; q[3] = acc[i][3];
    }
}

// ---------------- K6: reduce k-split partials ----------------
__global__ void k_redh()
{
    int i = blockIdx.x*256 + threadIdx.x;
    if (i < BB*DIMD) {
        float s = 0.f;
#pragma unroll
        for (int ks = 0; ks < 8; ks++) s += g_hp[(size_t)ks*(BB*DIMD) + i];
        g_h[i] = s;
    }
}

// ---------------- K7: BN1 stats per column e ----------------
__global__ void k_stats1(const float* __restrict__ gamma1, const float* __restrict__ beta1)
{
    __shared__ float r0[256];
    int e = blockIdx.x, t = threadIdx.x;
    float s = 0.f, sq = 0.f;
    for (int b = t; b < BB; b += 256) {
        float v = g_h[b*DIMD + e];
        s += v; sq += v*v;
    }
    float ts = blockReduce256(s, r0);
    float tq = blockReduce256(sq, r0);
    if (t == 0) {
        float mu  = ts * (1.f/2048.f);
        float var = tq * (1.f/2048.f) - mu*mu;
        float rs  = rsqrtf(var + BNEPS);
        float sc  = rs * gamma1[e];
        g_scale1[e] = sc;
        g_shift1[e] = beta1[e] - mu*sc;
    }
}

// ---------------- K8: apply BN1 ----------------
__global__ void k_hnorm()
{
    int i = blockIdx.x*256 + threadIdx.x;
    if (i < BB*DIMD) {
        int d = i % DIMD;
        g_hn[i] = g_h[i] * g_scale1[d] + g_shift1[d];
    }
}

// ---------------- K9: GEMM-B  pred = h_n @ E^T ----------------
// block: 128 b x 128 n, K=200 in 4 chunks of 50. 256 threads, thread tile 8b x 8n.
#define SMEM_B 79200
__global__ void __launch_bounds__(256, 2) k_gemmB(const float* __restrict__ E,
                                                  float* __restrict__ out)
{
    extern __shared__ float smB[];
    ull*   hn = (ull*)smB;          // 50 x 132 packed (v,v)
    float* es = smB + 13200;        // 50 x 132

    int t  = threadIdx.x;
    int b0 = blockIdx.x * 128;
    int n0 = blockIdx.y * 128;
    int tn = t % 16, tb = t / 16;
    int nn = tn * 8, bb = tb * 8;

    ull acc[8][4];
#pragma unroll
    for (int i = 0; i < 8; i++)
#pragma unroll
        for (int j = 0; j < 4; j++) acc[i][j] = 0ULL;

    for (int kc = 0; kc < 4; kc++) {
        int k0 = kc * 50;
        __syncthreads();
        for (int i = t; i < 6400; i += 256) {
            int b = i / 50, k = i % 50;
            hn[k*132 + b] = pack2(g_hn[(b0 + b)*DIMD + k0 + k]);
        }
        for (int i = t; i < 6400; i += 256) {
            int n = i / 50, k = i % 50;
            int gn = n0 + n;
            es[k*132 + n] = (gn < NENT) ? E[(size_t)gn*DIMD + k0 + k] : 0.f;
        }
        __syncthreads();
#pragma unroll 2
        for (int k = 0; k < 50; k++) {
            const ull*   ar = hn + k*132 + bb;
            const float* wr = es + k*132 + nn;
            ulonglong2 a01 = *(const ulonglong2*)(ar);
            ulonglong2 a23 = *(const ulonglong2*)(ar + 2);
            ulonglong2 a45 = *(const ulonglong2*)(ar + 4);
            ulonglong2 a67 = *(const ulonglong2*)(ar + 6);
            ulonglong2 w01 = *(const ulonglong2*)(wr);
            ulonglong2 w23 = *(const ulonglong2*)(wr + 4);
            ull a[8] = {a01.x, a01.y, a23.x, a23.y, a45.x, a45.y, a67.x, a67.y};
            ull w[4] = {w01.x, w01.y, w23.x, w23.y};
#pragma unroll
            for (int i = 0; i < 8; i++)
#pragma unroll
                for (int j = 0; j < 4; j++) fma2(acc[i][j], a[i], w[j]);
        }
    }

    if (n0 + 128 <= NENT) {
#pragma unroll
        for (int i = 0; i < 8; i++) {
            ull* q = (ull*)(out + (size_t)(b0 + bb + i)*NENT + n0 + nn);
            q[0] = acc[i][0]; q[1] = acc[i][1]; q[2] = acc[i][2]; q[3] = acc[i][3];
        }
    } else {
#pragma unroll
        for (int i = 0; i < 8; i++) {
            size_t row = (size_t)(b0 + bb + i)*NENT;
#pragma unroll
            for (int j = 0; j < 4; j++) {
                float2 f = *(float2*)&acc[i][j];
                int n = n0 + nn + 2*j;
                if (n     < NENT) out[row + n]     = f.x;
                if (n + 1 < NENT) out[row + n + 1] = f.y;
            }
        }
    }
}

// ---------------- launch ----------------
extern "C" void kernel_launch(void* const* d_in, const int* in_sizes, int n_in,
                              void* d_out, int out_size)
{
    const int*   x   = (const int*)d_in[0];
    const float* E   = (const float*)d_in[1];
    const float* R   = (const float*)d_in[2];
    const float* RnT = (const float*)d_in[3];
    const float* T   = (const float*)d_in[4];
    const float* W   = (const float*)d_in[5];
    const float* g0  = (const float*)d_in[6];
    const float* be0 = (const float*)d_in[7];
    const float* g1  = (const float*)d_in[8];
    const float* be1 = (const float*)d_in[9];
    float* out = (float*)d_out;

    cudaFuncSetAttribute(k_gemmA, cudaFuncAttributeMaxDynamicSharedMemorySize, SMEM_A);
    cudaFuncSetAttribute(k_gemmB, cudaFuncAttributeMaxDynamicSharedMemorySize, SMEM_B);

    k_gather<<<128, 256>>>(x, E, R, RnT, T);
    k_stats0<<<1, 256>>>(g0, be0);
    k_norm4<<<512, 256>>>(W);
    k_finreg<<<1, 256>>>(out);
    k_gemmA<<<dim3(32, 8), 200, SMEM_A>>>(W);
    k_redh<<<1600, 256>>>();
    k_stats1<<<200, 256>>>(g1, be1);
    k_hnorm<<<1600, 256>>>();
    k_gemmB<<<dim3(16, 782), 256, SMEM_B>>>(E, out);
    cudaMemcpyAsync(out + OFF_T, T, 80000 * sizeof(float), cudaMemcpyDeviceToDevice);
}

// round 4
// speedup vs baseline: 1.7759x; 1.7759x over previous
#include <cuda_runtime.h>
#include <cuda_bf16.h>
#include <cstdint>

typedef unsigned long long ull;

#define BB    2048
#define DIMD  200
#define NENT  100000
#define NENTP 100096
#define WELEM 8000000
#define BNEPS 1e-5f

#define OFF_PRED 0LL
#define OFF_REG  204800000LL
#define OFF_T    204800005LL

// ---------------- device scratch ----------------
__device__ float g_lhs  [BB*DIMD];
__device__ float g_relt [BB*DIMD];
__device__ float g_lhsn [BB*DIMD];
__device__ float g_colp [128*2*DIMD];
__device__ float g_s4p  [128*3];
__device__ float g_scale0[DIMD];
__device__ float g_shift0[DIMD];
__device__ float g_regsums[4];
__device__ float g_n4p  [512*2];
__device__ float g_hp   [8*BB*DIMD];
__device__ float g_h    [BB*DIMD];
__device__ float g_scale1[DIMD];
__device__ float g_shift1[DIMD];
// bf16 hi/lo splits, col-padded to 256 (E row-padded to 100096)
__device__ __nv_bfloat16 g_Ehi[(size_t)NENTP*256];
__device__ __nv_bfloat16 g_Elo[(size_t)NENTP*256];
__device__ __nv_bfloat16 g_hhi[BB*256];
__device__ __nv_bfloat16 g_hlo[BB*256];

// ---------------- helpers ----------------
__device__ __forceinline__ void fma2(ull& d, ull a, ull b) {
    asm("fma.rn.f32x2 %0, %1, %2, %0;" : "+l"(d) : "l"(a), "l"(b));
}
__device__ __forceinline__ ull pack2(float x) {
    ull r;
    asm("mov.b64 %0, {%1, %1};" : "=l"(r) : "r"(__float_as_uint(x)));
    return r;
}
__device__ __forceinline__ uint32_t smem_u32(const void* p) {
    uint32_t a;
    asm("{ .reg .u64 t; cvta.to.shared.u64 t, %1; cvt.u32.u64 %0, t; }" : "=r"(a) : "l"(p));
    return a;
}
__device__ __forceinline__ void cp16(uint32_t dst, const void* src) {
    asm volatile("cp.async.cg.shared.global [%0], [%1], 16;" :: "r"(dst), "l"(src));
}
#define CP_COMMIT() asm volatile("cp.async.commit_group;" ::: "memory")
#define CP_WAIT(n)  asm volatile("cp.async.wait_group %0;" :: "n"(n) : "memory")

__device__ __forceinline__ void ldsm_x4(uint32_t& r0, uint32_t& r1, uint32_t& r2, uint32_t& r3, uint32_t addr) {
    asm volatile("ldmatrix.sync.aligned.m8n8.x4.shared.b16 {%0,%1,%2,%3}, [%4];"
        : "=r"(r0), "=r"(r1), "=r"(r2), "=r"(r3) : "r"(addr));
}
__device__ __forceinline__ void mma16816(float* c, const uint32_t* a, uint32_t b0, uint32_t b1) {
    asm volatile("mma.sync.aligned.m16n8k16.row.col.f32.bf16.bf16.f32 "
        "{%0,%1,%2,%3}, {%4,%5,%6,%7}, {%8,%9}, {%0,%1,%2,%3};"
        : "+f"(c[0]), "+f"(c[1]), "+f"(c[2]), "+f"(c[3])
        : "r"(a[0]), "r"(a[1]), "r"(a[2]), "r"(a[3]), "r"(b0), "r"(b1));
}
#define SWZ128(x) ((x) ^ (((x) >> 3) & 0x70))

__device__ __forceinline__ float blockReduce256(float v, float* red) {
    int t = threadIdx.x;
    red[t] = v; __syncthreads();
#pragma unroll
    for (int s = 128; s > 0; s >>= 1) {
        if (t < s) red[t] += red[t + s];
        __syncthreads();
    }
    float r = red[0]; __syncthreads();
    return r;
}

// ---------------- K1: gather + BN0 partials + norm4 partials ----------------
__global__ void k_gather(const int* __restrict__ x,
                         const float* __restrict__ E,
                         const float* __restrict__ R,
                         const float* __restrict__ RnT,
                         const float* __restrict__ T)
{
    __shared__ float red[256];
    int t = threadIdx.x;
    int d = t;
    float cs = 0.f, cq = 0.f, s_rt = 0.f, s_rn = 0.f, s_rh = 0.f;
    if (d < DIMD) {
#pragma unroll 4
        for (int i = 0; i < 16; i++) {
            int b = blockIdx.x * 16 + i;
            int i0 = x[b*4+0], i1 = x[b*4+1], i2 = x[b*4+2], i3 = x[b*4+3];
            float l  = E[(size_t)i0*DIMD + d];
            float rt = R[(size_t)i1*DIMD + d] * T[(size_t)i3*DIMD + d];
            float rn = RnT[(size_t)i1*DIMD + d];
            float rh = E[(size_t)i2*DIMD + d];
            g_lhs [b*DIMD + d] = l;
            g_relt[b*DIMD + d] = rt;
            cs += l; cq += l*l;
            float a = rt*rt;  s_rt += a*a;
            float bq = rn*rn; s_rn += bq*bq;
            float cc = rh*rh; s_rh += cc*cc;
        }
        g_colp[blockIdx.x*2*DIMD + d]        = cs;
        g_colp[blockIdx.x*2*DIMD + DIMD + d] = cq;
    }
    float r0 = blockReduce256(s_rt, red);
    float r1 = blockReduce256(s_rn, red);
    float r2 = blockReduce256(s_rh, red);
    if (t == 0) {
        g_s4p[blockIdx.x*3 + 0] = r0;
        g_s4p[blockIdx.x*3 + 1] = r1;
        g_s4p[blockIdx.x*3 + 2] = r2;
    }
}

// ---------------- K2: BN0 stats + reg sums ----------------
__global__ void k_stats0(const float* __restrict__ gamma0, const float* __restrict__ beta0)
{
    int t = threadIdx.x;
    if (t < DIMD) {
        float s = 0.f, sq = 0.f;
        for (int k = 0; k < 128; k++) {
            s  += g_colp[k*2*DIMD + t];
            sq += g_colp[k*2*DIMD + DIMD + t];
        }
        float mu  = s  * (1.f/2048.f);
        float var = sq * (1.f/2048.f) - mu*mu;
        float rs  = rsqrtf(var + BNEPS);
        float sc  = rs * gamma0[t];
        g_scale0[t] = sc;
        g_shift0[t] = beta0[t] - mu*sc;
    } else if (t < DIMD + 3) {
        int j = t - DIMD;
        float s = 0.f;
        for (int k = 0; k < 128; k++) s += g_s4p[k*3 + j];
        g_regsums[j + 1] = s;
    }
}

// ---------------- K3: norm4(W) + norm4(lhs_n), materialize lhs_n ----------------
__global__ void k_norm4(const float* __restrict__ W)
{
    __shared__ float red[256];
    int t = threadIdx.x;
    float pw = 0.f, pl = 0.f;
    const int TOT = WELEM + BB*DIMD;
    for (int idx = blockIdx.x*256 + t; idx < TOT; idx += 512*256) {
        if (idx < WELEM) {
            float v = W[idx]; float v2 = v*v; pw += v2*v2;
        } else {
            int i = idx - WELEM;
            int d = i % DIMD;
            float v = g_lhs[i] * g_scale0[d] + g_shift0[d];
            g_lhsn[i] = v;
            float v2 = v*v; pl += v2*v2;
        }
    }
    float rl = blockReduce256(pl, red);
    float rw = blockReduce256(pw, red);
    if (t == 0) {
        g_n4p[blockIdx.x*2 + 0] = rl;
        g_n4p[blockIdx.x*2 + 1] = rw;
    }
}

// ---------------- K4: write reg[5] ----------------
__global__ void k_finreg(float* __restrict__ out)
{
    __shared__ float red[256];
    int t = threadIdx.x;
    float a = 0.f, b = 0.f;
    for (int i = t; i < 512; i += 256) { a += g_n4p[2*i]; b += g_n4p[2*i + 1]; }
    float sl = blockReduce256(a, red);
    float sw = blockReduce256(b, red);
    if (t == 0) {
        out[OFF_REG + 0] = powf(sl,           0.25f);
        out[OFF_REG + 1] = powf(g_regsums[1], 0.25f);
        out[OFF_REG + 2] = powf(g_regsums[2], 0.25f);
        out[OFF_REG + 3] = powf(g_regsums[3], 0.25f);
        out[OFF_REG + 4] = powf(sw,           0.25f);
    }
}

// ---------------- K5: GEMM-A (FFMA2) ----------------
#define SMEM_A 110080
__global__ void __launch_bounds__(200, 2) k_gemmA(const float* __restrict__ W)
{
    extern __shared__ float smA[];
    float* u_sm  = smA;
    float* v_sm  = smA + 1600;
    float* w_sm  = smA + 14400;
    ull*   c_dup = (ull*)(smA + 22400);

    int t   = threadIdx.x;
    int b0  = blockIdx.x * 64;
    int kk0 = blockIdx.y * 25;

    for (int i = t; i < 1600; i += 200) {
        int b = i / 25, j = i % 25;
        u_sm[i] = g_relt[(b0 + b)*DIMD + kk0 + j];
    }
    for (int i = t; i < 12800; i += 200) {
        v_sm[i] = g_lhsn[(b0 + (i/200))*DIMD + (i%200)];
    }
    __syncthreads();

    int et = t % 25, bt = t / 25;
    int eb = et * 8, bb = bt * 8;

    ull acc[8][4];
#pragma unroll
    for (int i = 0; i < 8; i++)
#pragma unroll
        for (int j = 0; j < 4; j++) acc[i][j] = 0ULL;

    for (int kk = 0; kk < 25; kk++) {
        const float* Wk = W + (size_t)(kk0 + kk) * 40000;
        for (int c = 0; c < 5; c++) {
            int dd0 = c * 40;
            __syncthreads();
            {
                const float4* Wg = (const float4*)(Wk + dd0*200);
                float4* wd = (float4*)w_sm;
                for (int i = t; i < 2000; i += 200) wd[i] = Wg[i];
            }
            for (int i = t; i < 2560; i += 200) {
                int dd = i / 64, b = i % 64;
                c_dup[i] = pack2(u_sm[b*25 + kk] * v_sm[b*200 + dd0 + dd]);
            }
            __syncthreads();
#pragma unroll 2
            for (int dd = 0; dd < 40; dd++) {
                const ull*   cr = c_dup + dd*64 + bb;
                const float* wr = w_sm  + dd*200 + eb;
                ulonglong2 a01 = *(const ulonglong2*)(cr);
                ulonglong2 a23 = *(const ulonglong2*)(cr + 2);
                ulonglong2 a45 = *(const ulonglong2*)(cr + 4);
                ulonglong2 a67 = *(const ulonglong2*)(cr + 6);
                ulonglong2 w01 = *(const ulonglong2*)(wr);
                ulonglong2 w23 = *(const ulonglong2*)(wr + 4);
                ull a[8] = {a01.x, a01.y, a23.x, a23.y, a45.x, a45.y, a67.x, a67.y};
                ull w[4] = {w01.x, w01.y, w23.x, w23.y};
#pragma unroll
                for (int i = 0; i < 8; i++)
#pragma unroll
                    for (int j = 0; j < 4; j++) fma2(acc[i][j], a[i], w[j]);
            }
        }
    }

    float* base = g_hp + (size_t)blockIdx.y * (BB*DIMD);
#pragma unroll
    for (int i = 0; i < 8; i++) {
        ull* q = (ull*)(base + (size_t)(b0 + bb + i)*DIMD + eb);
        q[0] = acc[i][0]; q[1] = acc[i][1]; q[2] = acc[i][2]; q[3] = acc[i][3];
    }
}

// ---------------- K6: reduce k-split partials ----------------
__global__ void k_redh()
{
    int i = blockIdx.x*256 + threadIdx.x;
    if (i < BB*DIMD) {
        float s = 0.f;
#pragma unroll
        for (int ks = 0; ks < 8; ks++) s += g_hp[(size_t)ks*(BB*DIMD) + i];
        g_h[i] = s;
    }
}

// ---------------- K7: BN1 stats ----------------
__global__ void k_stats1(const float* __restrict__ gamma1, const float* __restrict__ beta1)
{
    __shared__ float r0[256];
    int e = blockIdx.x, t = threadIdx.x;
    float s = 0.f, sq = 0.f;
    for (int b = t; b < BB; b += 256) {
        float v = g_h[b*DIMD + e];
        s += v; sq += v*v;
    }
    float ts = blockReduce256(s, r0);
    float tq = blockReduce256(sq, r0);
    if (t == 0) {
        float mu  = ts * (1.f/2048.f);
        float var = tq * (1.f/2048.f) - mu*mu;
        float rs  = rsqrtf(var + BNEPS);
        float sc  = rs * gamma1[e];
        g_scale1[e] = sc;
        g_shift1[e] = beta1[e] - mu*sc;
    }
}

// ---------------- K8a: split E into bf16 hi/lo (padded) ----------------
__global__ void k_splitE(const float* __restrict__ E)
{
    int r = blockIdx.x;
    int c = threadIdx.x * 2;
    float v0 = 0.f, v1 = 0.f;
    if (r < NENT) {
        if (c < DIMD)     v0 = E[(size_t)r*DIMD + c];
        if (c + 1 < DIMD) v1 = E[(size_t)r*DIMD + c + 1];
    }
    __nv_bfloat16 h0 = __float2bfloat16(v0);
    __nv_bfloat16 h1 = __float2bfloat16(v1);
    __nv_bfloat16 l0 = __float2bfloat16(v0 - __bfloat162float(h0));
    __nv_bfloat16 l1 = __float2bfloat16(v1 - __bfloat162float(h1));
    size_t o = (size_t)r*256 + c;
    *(__nv_bfloat162*)&g_Ehi[o] = __nv_bfloat162(h0, h1);
    *(__nv_bfloat162*)&g_Elo[o] = __nv_bfloat162(l0, l1);
}

// ---------------- K8b: BN1 apply + split h_n into bf16 hi/lo ----------------
__global__ void k_hsplit()
{
    int b = blockIdx.x;
    int c = threadIdx.x * 2;
    float v0 = 0.f, v1 = 0.f;
    if (c < DIMD)     v0 = g_h[b*DIMD + c]     * g_scale1[c]     + g_shift1[c];
    if (c + 1 < DIMD) v1 = g_h[b*DIMD + c + 1] * g_scale1[c + 1] + g_shift1[c + 1];
    __nv_bfloat16 h0 = __float2bfloat16(v0);
    __nv_bfloat16 h1 = __float2bfloat16(v1);
    __nv_bfloat16 l0 = __float2bfloat16(v0 - __bfloat162float(h0));
    __nv_bfloat16 l1 = __float2bfloat16(v1 - __bfloat162float(h1));
    size_t o = (size_t)b*256 + c;
    *(__nv_bfloat162*)&g_hhi[o] = __nv_bfloat162(h0, h1);
    *(__nv_bfloat162*)&g_hlo[o] = __nv_bfloat162(l0, l1);
}

// ---------------- K9: GEMM-B on mma.sync (bf16, 3-term compensation) ----------------
// CTA: 256 b x 64 n. 8 warps = 4(b) x 2(n); warp tile 64b x 32n.
// K chunks of 64, 12 chunks (3 terms x 4), cp.async double-buffered.
#define ASTG 32768
#define BSTG 8192
#define STG  (ASTG + BSTG)
#define SMEM_B (2*STG + 1024)

__global__ void __launch_bounds__(256, 2) k_gemmB_mma(float* __restrict__ out)
{
    extern __shared__ char smraw[];
    uint32_t smem_base0 = smem_u32(smraw);
    uint32_t base = (smem_base0 + 1023) & ~1023u;

    int t = threadIdx.x;
    int lane = t & 31, wid = t >> 5;
    int wb = wid >> 1, wn = wid & 1;
    int n0 = blockIdx.x * 64;
    int b0 = blockIdx.y * 256;

    float acc[4][4][4];
#pragma unroll
    for (int i = 0; i < 4; i++)
#pragma unroll
        for (int j = 0; j < 4; j++)
#pragma unroll
            for (int q = 0; q < 4; q++) acc[i][j][q] = 0.f;

    // issue chunk 0
    {
        const __nv_bfloat16* Asrc = g_hhi;
        const __nv_bfloat16* Bsrc = g_Ehi;
        uint32_t ab = base, bb_ = base + ASTG;
#pragma unroll
        for (int j = 0; j < 8; j++) {
            int idx = t + 256*j;
            int row = idx >> 3, seg = idx & 7;
            cp16(ab + SWZ128(row*128 + seg*16), Asrc + (size_t)(b0 + row)*256 + seg*8);
        }
#pragma unroll
        for (int j = 0; j < 2; j++) {
            int idx = t + 256*j;
            int row = idx >> 3, seg = idx & 7;
            cp16(bb_ + SWZ128(row*128 + seg*16), Bsrc + (size_t)(n0 + row)*256 + seg*8);
        }
        CP_COMMIT();
    }

    for (int i = 0; i < 12; i++) {
        if (i + 1 < 12) {
            int term = (i+1) >> 2, kc = ((i+1) & 3) * 64;
            const __nv_bfloat16* Asrc = (term == 1) ? g_hlo : g_hhi;
            const __nv_bfloat16* Bsrc = (term == 2) ? g_Elo : g_Ehi;
            uint32_t ab = base + ((i+1)&1)*STG, bb_ = ab + ASTG;
#pragma unroll
            for (int j = 0; j < 8; j++) {
                int idx = t + 256*j;
                int row = idx >> 3, seg = idx & 7;
                cp16(ab + SWZ128(row*128 + seg*16), Asrc + (size_t)(b0 + row)*256 + kc + seg*8);
            }
#pragma unroll
            for (int j = 0; j < 2; j++) {
                int idx = t + 256*j;
                int row = idx >> 3, seg = idx & 7;
                cp16(bb_ + SWZ128(row*128 + seg*16), Bsrc + (size_t)(n0 + row)*256 + kc + seg*8);
            }
            CP_COMMIT();
            CP_WAIT(1);
        } else {
            CP_WAIT(0);
        }
        __syncthreads();

        uint32_t ab = base + (i&1)*STG, bb_ = ab + ASTG;
        int nst = ((i & 3) == 3) ? 1 : 4;   // kc=192: only k<208 valid (pad zeros beyond)
        for (int ks = 0; ks < nst; ks++) {
            uint32_t a[4][4];
            uint32_t bf[4][2];
            int rl = lane & 15;
            int ch = 2*ks + (lane >> 4);
#pragma unroll
            for (int mi = 0; mi < 4; mi++) {
                int row = wb*64 + mi*16 + rl;
                ldsm_x4(a[mi][0], a[mi][1], a[mi][2], a[mi][3], ab + SWZ128(row*128 + ch*16));
            }
#pragma unroll
            for (int nj = 0; nj < 2; nj++) {
                uint32_t r0, r1, r2, r3;
                int row = wn*32 + nj*16 + rl;
                ldsm_x4(r0, r1, r2, r3, bb_ + SWZ128(row*128 + ch*16));
                bf[nj*2+0][0] = r0; bf[nj*2+0][1] = r2;
                bf[nj*2+1][0] = r1; bf[nj*2+1][1] = r3;
            }
#pragma unroll
            for (int mi = 0; mi < 4; mi++)
#pragma unroll
                for (int ni = 0; ni < 4; ni++)
                    mma16816(acc[mi][ni], a[mi], bf[ni][0], bf[ni][1]);
        }
        __syncthreads();
    }

    // epilogue
    int g = lane >> 2, c2 = (lane & 3)*2;
#pragma unroll
    for (int mi = 0; mi < 4; mi++) {
#pragma unroll
        for (int ni = 0; ni < 4; ni++) {
            int col = n0 + wn*32 + ni*8 + c2;
            if (col < NENT) {
                size_t r0 = (size_t)(b0 + wb*64 + mi*16 + g) * NENT + col;
                size_t r1 = r0 + (size_t)8 * NENT;
                *(float2*)(out + r0) = make_float2(acc[mi][ni][0], acc[mi][ni][1]);
                *(float2*)(out + r1) = make_float2(acc[mi][ni][2], acc[mi][ni][3]);
            }
        }
    }
}

// ---------------- launch ----------------
extern "C" void kernel_launch(void* const* d_in, const int* in_sizes, int n_in,
                              void* d_out, int out_size)
{
    const int*   x   = (const int*)d_in[0];
    const float* E   = (const float*)d_in[1];
    const float* R   = (const float*)d_in[2];
    const float* RnT = (const float*)d_in[3];
    const float* T   = (const float*)d_in[4];
    const float* W   = (const float*)d_in[5];
    const float* g0  = (const float*)d_in[6];
    const float* be0 = (const float*)d_in[7];
    const float* g1  = (const float*)d_in[8];
    const float* be1 = (const float*)d_in[9];
    float* out = (float*)d_out;

    cudaFuncSetAttribute(k_gemmA,     cudaFuncAttributeMaxDynamicSharedMemorySize, SMEM_A);
    cudaFuncSetAttribute(k_gemmB_mma, cudaFuncAttributeMaxDynamicSharedMemorySize, SMEM_B);

    k_gather<<<128, 256>>>(x, E, R, RnT, T);
    k_stats0<<<1, 256>>>(g0, be0);
    k_norm4<<<512, 256>>>(W);
    k_finreg<<<1, 256>>>(out);
    k_splitE<<<NENTP, 128>>>(E);
    k_gemmA<<<dim3(32, 8), 200, SMEM_A>>>(W);
    k_redh<<<1600, 256>>>();
    k_stats1<<<200, 256>>>(g1, be1);
    k_hsplit<<<BB, 128>>>();
    k_gemmB_mma<<<dim3(1564, 8), 256, SMEM_B>>>(out);
    cudaMemcpyAsync(out + OFF_T, T, 80000 * sizeof(float), cudaMemcpyDeviceToDevice);
}

// round 5
// speedup vs baseline: 2.4213x; 1.3635x over previous
#include <cuda_runtime.h>
#include <cuda_bf16.h>
#include <cstdint>

typedef unsigned long long ull;

#define BB    2048
#define DIMD  200
#define NENT  100000
#define NENTP 100096
#define WELEM 8000000
#define KKD   40000
#define BNEPS 1e-5f

#define OFF_PRED 0LL
#define OFF_REG  204800000LL
#define OFF_T    204800005LL

#define NSPLIT 25

// ---------------- device scratch ----------------
__device__ float g_lhs  [BB*DIMD];
__device__ float g_relt [BB*DIMD];
__device__ float g_lhsn [BB*DIMD];
__device__ float g_colp [128*2*DIMD];
__device__ float g_s4p  [128*3];
__device__ float g_scale0[DIMD];
__device__ float g_shift0[DIMD];
__device__ float g_regsums[4];
__device__ float g_n4p  [512*2];
__device__ float g_h    [BB*DIMD];
__device__ float g_scale1[DIMD];
__device__ float g_shift1[DIMD];
// bf16 hi/lo splits
__device__ __nv_bfloat16 g_Ehi[(size_t)NENTP*256];
__device__ __nv_bfloat16 g_Elo[(size_t)NENTP*256];
__device__ __nv_bfloat16 g_hhi[BB*256];
__device__ __nv_bfloat16 g_hlo[BB*256];
// GEMM-A operands
__device__ __nv_bfloat16 g_Ahi[(size_t)BB*KKD];
__device__ __nv_bfloat16 g_Alo[(size_t)BB*KKD];
__device__ __nv_bfloat16 g_Wthi[(size_t)256*KKD];
__device__ __nv_bfloat16 g_Wtlo[(size_t)256*KKD];
__device__ float g_hpA[(size_t)NSPLIT*BB*256];

// ---------------- helpers ----------------
__device__ __forceinline__ uint32_t smem_u32(const void* p) {
    uint32_t a;
    asm("{ .reg .u64 t; cvta.to.shared.u64 t, %1; cvt.u32.u64 %0, t; }" : "=r"(a) : "l"(p));
    return a;
}
__device__ __forceinline__ void cp16(uint32_t dst, const void* src) {
    asm volatile("cp.async.cg.shared.global [%0], [%1], 16;" :: "r"(dst), "l"(src));
}
#define CP_COMMIT() asm volatile("cp.async.commit_group;" ::: "memory")
#define CP_WAIT(n)  asm volatile("cp.async.wait_group %0;" :: "n"(n) : "memory")

__device__ __forceinline__ void ldsm_x4(uint32_t& r0, uint32_t& r1, uint32_t& r2, uint32_t& r3, uint32_t addr) {
    asm volatile("ldmatrix.sync.aligned.m8n8.x4.shared.b16 {%0,%1,%2,%3}, [%4];"
        : "=r"(r0), "=r"(r1), "=r"(r2), "=r"(r3) : "r"(addr));
}
__device__ __forceinline__ void mma16816(float* c, const uint32_t* a, uint32_t b0, uint32_t b1) {
    asm volatile("mma.sync.aligned.m16n8k16.row.col.f32.bf16.bf16.f32 "
        "{%0,%1,%2,%3}, {%4,%5,%6,%7}, {%8,%9}, {%0,%1,%2,%3};"
        : "+f"(c[0]), "+f"(c[1]), "+f"(c[2]), "+f"(c[3])
        : "r"(a[0]), "r"(a[1]), "r"(a[2]), "r"(a[3]), "r"(b0), "r"(b1));
}
#define SWZ128(x) ((x) ^ (((x) >> 3) & 0x70))

__device__ __forceinline__ float blockReduce256(float v, float* red) {
    int t = threadIdx.x;
    red[t] = v; __syncthreads();
#pragma unroll
    for (int s = 128; s > 0; s >>= 1) {
        if (t < s) red[t] += red[t + s];
        __syncthreads();
    }
    float r = red[0]; __syncthreads();
    return r;
}

// ---------------- K1: gather + BN0 partials + norm4 partials ----------------
__global__ void k_gather(const int* __restrict__ x,
                         const float* __restrict__ E,
                         const float* __restrict__ R,
                         const float* __restrict__ RnT,
                         const float* __restrict__ T)
{
    __shared__ float red[256];
    int t = threadIdx.x;
    int d = t;
    float cs = 0.f, cq = 0.f, s_rt = 0.f, s_rn = 0.f, s_rh = 0.f;
    if (d < DIMD) {
#pragma unroll 4
        for (int i = 0; i < 16; i++) {
            int b = blockIdx.x * 16 + i;
            int i0 = x[b*4+0], i1 = x[b*4+1], i2 = x[b*4+2], i3 = x[b*4+3];
            float l  = E[(size_t)i0*DIMD + d];
            float rt = R[(size_t)i1*DIMD + d] * T[(size_t)i3*DIMD + d];
            float rn = RnT[(size_t)i1*DIMD + d];
            float rh = E[(size_t)i2*DIMD + d];
            g_lhs [b*DIMD + d] = l;
            g_relt[b*DIMD + d] = rt;
            cs += l; cq += l*l;
            float a = rt*rt;  s_rt += a*a;
            float bq = rn*rn; s_rn += bq*bq;
            float cc = rh*rh; s_rh += cc*cc;
        }
        g_colp[blockIdx.x*2*DIMD + d]        = cs;
        g_colp[blockIdx.x*2*DIMD + DIMD + d] = cq;
    }
    float r0 = blockReduce256(s_rt, red);
    float r1 = blockReduce256(s_rn, red);
    float r2 = blockReduce256(s_rh, red);
    if (t == 0) {
        g_s4p[blockIdx.x*3 + 0] = r0;
        g_s4p[blockIdx.x*3 + 1] = r1;
        g_s4p[blockIdx.x*3 + 2] = r2;
    }
}

// ---------------- K2: BN0 stats + reg sums ----------------
__global__ void k_stats0(const float* __restrict__ gamma0, const float* __restrict__ beta0)
{
    int t = threadIdx.x;
    if (t < DIMD) {
        float s = 0.f, sq = 0.f;
        for (int k = 0; k < 128; k++) {
            s  += g_colp[k*2*DIMD + t];
            sq += g_colp[k*2*DIMD + DIMD + t];
        }
        float mu  = s  * (1.f/2048.f);
        float var = sq * (1.f/2048.f) - mu*mu;
        float rs  = rsqrtf(var + BNEPS);
        float sc  = rs * gamma0[t];
        g_scale0[t] = sc;
        g_shift0[t] = beta0[t] - mu*sc;
    } else if (t < DIMD + 3) {
        int j = t - DIMD;
        float s = 0.f;
        for (int k = 0; k < 128; k++) s += g_s4p[k*3 + j];
        g_regsums[j + 1] = s;
    }
}

// ---------------- K3: norm4(W) + norm4(lhs_n), materialize lhs_n ----------------
__global__ void k_norm4(const float* __restrict__ W)
{
    __shared__ float red[256];
    int t = threadIdx.x;
    float pw = 0.f, pl = 0.f;
    const int TOT = WELEM + BB*DIMD;
    for (int idx = blockIdx.x*256 + t; idx < TOT; idx += 512*256) {
        if (idx < WELEM) {
            float v = W[idx]; float v2 = v*v; pw += v2*v2;
        } else {
            int i = idx - WELEM;
            int d = i % DIMD;
            float v = g_lhs[i] * g_scale0[d] + g_shift0[d];
            g_lhsn[i] = v;
            float v2 = v*v; pl += v2*v2;
        }
    }
    float rl = blockReduce256(pl, red);
    float rw = blockReduce256(pw, red);
    if (t == 0) {
        g_n4p[blockIdx.x*2 + 0] = rl;
        g_n4p[blockIdx.x*2 + 1] = rw;
    }
}

// ---------------- K4: write reg[5] ----------------
__global__ void k_finreg(float* __restrict__ out)
{
    __shared__ float red[256];
    int t = threadIdx.x;
    float a = 0.f, b = 0.f;
    for (int i = t; i < 512; i += 256) { a += g_n4p[2*i]; b += g_n4p[2*i + 1]; }
    float sl = blockReduce256(a, red);
    float sw = blockReduce256(b, red);
    if (t == 0) {
        out[OFF_REG + 0] = powf(sl,           0.25f);
        out[OFF_REG + 1] = powf(g_regsums[1], 0.25f);
        out[OFF_REG + 2] = powf(g_regsums[2], 0.25f);
        out[OFF_REG + 3] = powf(g_regsums[3], 0.25f);
        out[OFF_REG + 4] = powf(sw,           0.25f);
    }
}

// ---------------- K5a: build A' = relt (x) lhsn, bf16 hi/lo ----------------
__global__ void k_prepA()
{
    __shared__ float sr[DIMD], sl[DIMD];
    int b = blockIdx.x, t = threadIdx.x;
    if (t < DIMD) { sr[t] = g_relt[b*DIMD + t]; sl[t] = g_lhsn[b*DIMD + t]; }
    __syncthreads();
    size_t rowo = (size_t)b * KKD;
    for (int i2 = 2*t; i2 < KKD; i2 += 512) {
        int k = i2 / DIMD, d = i2 - k*DIMD;   // DIMD even -> pair never straddles k
        float a0 = sr[k]*sl[d];
        float a1 = sr[k]*sl[d+1];
        __nv_bfloat16 h0 = __float2bfloat16(a0);
        __nv_bfloat16 h1 = __float2bfloat16(a1);
        __nv_bfloat16 l0 = __float2bfloat16(a0 - __bfloat162float(h0));
        __nv_bfloat16 l1 = __float2bfloat16(a1 - __bfloat162float(h1));
        *(__nv_bfloat162*)&g_Ahi[rowo + i2] = __nv_bfloat162(h0, h1);
        *(__nv_bfloat162*)&g_Alo[rowo + i2] = __nv_bfloat162(l0, l1);
    }
}

// ---------------- K5b: W -> Wt (transposed, bf16 hi/lo, e padded to 256) ----------------
#define SPLITW_SMEM (64*DIMD*4)
__global__ void k_splitW(const float* __restrict__ W)
{
    extern __shared__ char swraw[];
    float* sm = (float*)swraw;      // 64 x 200
    int t = threadIdx.x;
    int kd0 = blockIdx.x * 64;
    for (int i = t; i < 64*DIMD; i += 256)
        sm[i] = W[(size_t)kd0*DIMD + i];
    __syncthreads();
    for (int idx = t; idx < 256*64; idx += 256) {
        int e = idx >> 6, kd = idx & 63;
        float v = (e < DIMD) ? sm[kd*DIMD + e] : 0.f;
        __nv_bfloat16 h = __float2bfloat16(v);
        g_Wthi[(size_t)e*KKD + kd0 + kd] = h;
        g_Wtlo[(size_t)e*KKD + kd0 + kd] = __float2bfloat16(v - __bfloat162float(h));
    }
}

// ---------------- K5c: GEMM-A via mma.sync ----------------
// CTA: 128 b x 256 n(e, padded), K-slice 1600 (25 chunks of 64), 512 thr.
// 16 warps = 4b x 4n; warp 32b x 64n. 3 compensation passes per chunk.
#define GA_STG 98304
#define SMEM_GA (2*GA_STG + 1024)
__global__ void __launch_bounds__(512, 1) k_gemmA_mma()
{
    extern __shared__ char smrawA[];
    uint32_t base = (smem_u32(smrawA) + 1023) & ~1023u;

    int t = threadIdx.x;
    int lane = t & 31, wid = t >> 5;
    int wb = wid >> 2, wn = wid & 3;
    int b0  = blockIdx.x * 128;
    int kd0 = blockIdx.y * 1600;

    float acc[2][8][4];
#pragma unroll
    for (int i = 0; i < 2; i++)
#pragma unroll
        for (int j = 0; j < 8; j++)
#pragma unroll
            for (int q = 0; q < 4; q++) acc[i][j][q] = 0.f;

    // prefetch chunk 0
    {
        uint32_t st = base;
#pragma unroll
        for (int j = 0; j < 2; j++) {
            int idx = t + 512*j;
            int row = idx >> 3, seg = idx & 7;
            size_t src = (size_t)(b0 + row)*KKD + kd0 + seg*8;
            cp16(st +         SWZ128(row*128 + seg*16), g_Ahi + src);
            cp16(st + 16384 + SWZ128(row*128 + seg*16), g_Alo + src);
        }
#pragma unroll
        for (int j = 0; j < 4; j++) {
            int idx = t + 512*j;
            int row = idx >> 3, seg = idx & 7;
            size_t src = (size_t)row*KKD + kd0 + seg*8;
            cp16(st + 32768 + SWZ128(row*128 + seg*16), g_Wthi + src);
            cp16(st + 65536 + SWZ128(row*128 + seg*16), g_Wtlo + src);
        }
        CP_COMMIT();
    }

    for (int c = 0; c < 25; c++) {
        if (c + 1 < 25) {
            int kc = (c+1)*64;
            uint32_t st = base + ((c+1)&1)*GA_STG;
#pragma unroll
            for (int j = 0; j < 2; j++) {
                int idx = t + 512*j;
                int row = idx >> 3, seg = idx & 7;
                size_t src = (size_t)(b0 + row)*KKD + kd0 + kc + seg*8;
                cp16(st +         SWZ128(row*128 + seg*16), g_Ahi + src);
                cp16(st + 16384 + SWZ128(row*128 + seg*16), g_Alo + src);
            }
#pragma unroll
            for (int j = 0; j < 4; j++) {
                int idx = t + 512*j;
                int row = idx >> 3, seg = idx & 7;
                size_t src = (size_t)row*KKD + kd0 + kc + seg*8;
                cp16(st + 32768 + SWZ128(row*128 + seg*16), g_Wthi + src);
                cp16(st + 65536 + SWZ128(row*128 + seg*16), g_Wtlo + src);
            }
            CP_COMMIT();
            CP_WAIT(1);
        } else {
            CP_WAIT(0);
        }
        __syncthreads();

        uint32_t st = base + (c&1)*GA_STG;
#pragma unroll
        for (int p = 0; p < 3; p++) {
            uint32_t ab  = st + ((p == 1) ? 16384 : 0);
            uint32_t bb_ = st + 32768 + ((p == 2) ? 32768 : 0);
            int rl = lane & 15;
            for (int ks = 0; ks < 4; ks++) {
                int ch = 2*ks + (lane >> 4);
                uint32_t a[2][4];
#pragma unroll
                for (int mi = 0; mi < 2; mi++) {
                    int row = wb*32 + mi*16 + rl;
                    ldsm_x4(a[mi][0], a[mi][1], a[mi][2], a[mi][3], ab + SWZ128(row*128 + ch*16));
                }
                uint32_t bf[8][2];
#pragma unroll
                for (int nj = 0; nj < 4; nj++) {
                    uint32_t r0, r1, r2, r3;
                    int row = wn*64 + nj*16 + rl;
                    ldsm_x4(r0, r1, r2, r3, bb_ + SWZ128(row*128 + ch*16));
                    bf[nj*2+0][0] = r0; bf[nj*2+0][1] = r2;
                    bf[nj*2+1][0] = r1; bf[nj*2+1][1] = r3;
                }
#pragma unroll
                for (int mi = 0; mi < 2; mi++)
#pragma unroll
                    for (int ni = 0; ni < 8; ni++)
                        mma16816(acc[mi][ni], a[mi], bf[ni][0], bf[ni][1]);
            }
        }
        __syncthreads();
    }

    // store partials to g_hpA[split][b][n], n stride 256
    float* dst = g_hpA + (size_t)blockIdx.y * (BB*256);
    int g = lane >> 2, c2 = (lane & 3)*2;
#pragma unroll
    for (int mi = 0; mi < 2; mi++) {
#pragma unroll
        for (int ni = 0; ni < 8; ni++) {
            int col = wn*64 + ni*8 + c2;
            if (col < DIMD) {
                size_t r0 = (size_t)(b0 + wb*32 + mi*16 + g) * 256 + col;
                *(float2*)(dst + r0)         = make_float2(acc[mi][ni][0], acc[mi][ni][1]);
                *(float2*)(dst + r0 + 8*256) = make_float2(acc[mi][ni][2], acc[mi][ni][3]);
            }
        }
    }
}

// ---------------- K6: reduce k-split partials ----------------
__global__ void k_redhA()
{
    int i = blockIdx.x*256 + threadIdx.x;
    if (i < BB*DIMD) {
        int b = i / DIMD, n = i - b*DIMD;
        float s = 0.f;
#pragma unroll
        for (int ks = 0; ks < NSPLIT; ks++)
            s += g_hpA[(size_t)ks*(BB*256) + (size_t)b*256 + n];
        g_h[i] = s;
    }
}

// ---------------- K7: BN1 stats ----------------
__global__ void k_stats1(const float* __restrict__ gamma1, const float* __restrict__ beta1)
{
    __shared__ float r0[256];
    int e = blockIdx.x, t = threadIdx.x;
    float s = 0.f, sq = 0.f;
    for (int b = t; b < BB; b += 256) {
        float v = g_h[b*DIMD + e];
        s += v; sq += v*v;
    }
    float ts = blockReduce256(s, r0);
    float tq = blockReduce256(sq, r0);
    if (t == 0) {
        float mu  = ts * (1.f/2048.f);
        float var = tq * (1.f/2048.f) - mu*mu;
        float rs  = rsqrtf(var + BNEPS);
        float sc  = rs * gamma1[e];
        g_scale1[e] = sc;
        g_shift1[e] = beta1[e] - mu*sc;
    }
}

// ---------------- K8a: split E into bf16 hi/lo (padded) ----------------
__global__ void k_splitE(const float* __restrict__ E)
{
    int r = blockIdx.x;
    int c = threadIdx.x * 2;
    float v0 = 0.f, v1 = 0.f;
    if (r < NENT) {
        if (c < DIMD)     v0 = E[(size_t)r*DIMD + c];
        if (c + 1 < DIMD) v1 = E[(size_t)r*DIMD + c + 1];
    }
    __nv_bfloat16 h0 = __float2bfloat16(v0);
    __nv_bfloat16 h1 = __float2bfloat16(v1);
    __nv_bfloat16 l0 = __float2bfloat16(v0 - __bfloat162float(h0));
    __nv_bfloat16 l1 = __float2bfloat16(v1 - __bfloat162float(h1));
    size_t o = (size_t)r*256 + c;
    *(__nv_bfloat162*)&g_Ehi[o] = __nv_bfloat162(h0, h1);
    *(__nv_bfloat162*)&g_Elo[o] = __nv_bfloat162(l0, l1);
}

// ---------------- K8b: BN1 apply + split h_n into bf16 hi/lo ----------------
__global__ void k_hsplit()
{
    int b = blockIdx.x;
    int c = threadIdx.x * 2;
    float v0 = 0.f, v1 = 0.f;
    if (c < DIMD)     v0 = g_h[b*DIMD + c]     * g_scale1[c]     + g_shift1[c];
    if (c + 1 < DIMD) v1 = g_h[b*DIMD + c + 1] * g_scale1[c + 1] + g_shift1[c + 1];
    __nv_bfloat16 h0 = __float2bfloat16(v0);
    __nv_bfloat16 h1 = __float2bfloat16(v1);
    __nv_bfloat16 l0 = __float2bfloat16(v0 - __bfloat162float(h0));
    __nv_bfloat16 l1 = __float2bfloat16(v1 - __bfloat162float(h1));
    size_t o = (size_t)b*256 + c;
    *(__nv_bfloat162*)&g_hhi[o] = __nv_bfloat162(h0, h1);
    *(__nv_bfloat162*)&g_hlo[o] = __nv_bfloat162(l0, l1);
}

// ---------------- K9: GEMM-B on mma.sync ----------------
// CTA: 256 b x 64 n. 8 warps = 4(b) x 2(n); warp 64b x 32n.
// 4 K-chunks of 64, each loaded once (hi+lo), 3 mma passes.
#define GB_STG 81920
#define SMEM_GB (2*GB_STG + 1024)
__global__ void __launch_bounds__(256, 1) k_gemmB_mma(float* __restrict__ out)
{
    extern __shared__ char smrawB[];
    uint32_t base = (smem_u32(smrawB) + 1023) & ~1023u;

    int t = threadIdx.x;
    int lane = t & 31, wid = t >> 5;
    int wb = wid >> 1, wn = wid & 1;
    int n0 = blockIdx.x * 64;
    int b0 = blockIdx.y * 256;

    float acc[4][4][4];
#pragma unroll
    for (int i = 0; i < 4; i++)
#pragma unroll
        for (int j = 0; j < 4; j++)
#pragma unroll
            for (int q = 0; q < 4; q++) acc[i][j][q] = 0.f;

    // prefetch chunk 0
    {
        uint32_t st = base;
#pragma unroll
        for (int j = 0; j < 8; j++) {
            int idx = t + 256*j;
            int row = idx >> 3, seg = idx & 7;
            size_t src = (size_t)(b0 + row)*256 + seg*8;
            cp16(st +         SWZ128(row*128 + seg*16), g_hhi + src);
            cp16(st + 32768 + SWZ128(row*128 + seg*16), g_hlo + src);
        }
#pragma unroll
        for (int j = 0; j < 2; j++) {
            int idx = t + 256*j;
            int row = idx >> 3, seg = idx & 7;
            size_t src = (size_t)(n0 + row)*256 + seg*8;
            cp16(st + 65536 + SWZ128(row*128 + seg*16), g_Ehi + src);
            cp16(st + 73728 + SWZ128(row*128 + seg*16), g_Elo + src);
        }
        CP_COMMIT();
    }

    for (int c = 0; c < 4; c++) {
        if (c + 1 < 4) {
            int kc = (c+1)*64;
            uint32_t st = base + ((c+1)&1)*GB_STG;
#pragma unroll
            for (int j = 0; j < 8; j++) {
                int idx = t + 256*j;
                int row = idx >> 3, seg = idx & 7;
                size_t src = (size_t)(b0 + row)*256 + kc + seg*8;
                cp16(st +         SWZ128(row*128 + seg*16), g_hhi + src);
                cp16(st + 32768 + SWZ128(row*128 + seg*16), g_hlo + src);
            }
#pragma unroll
            for (int j = 0; j < 2; j++) {
                int idx = t + 256*j;
                int row = idx >> 3, seg = idx & 7;
                size_t src = (size_t)(n0 + row)*256 + kc + seg*8;
                cp16(st + 65536 + SWZ128(row*128 + seg*16), g_Ehi + src);
                cp16(st + 73728 + SWZ128(row*128 + seg*16), g_Elo + src);
            }
            CP_COMMIT();
            CP_WAIT(1);
        } else {
            CP_WAIT(0);
        }
        __syncthreads();

        uint32_t st = base + (c&1)*GB_STG;
        int nst = (c == 3) ? 1 : 4;   // k >= 208 is zero padding
#pragma unroll
        for (int p = 0; p < 3; p++) {
            uint32_t ab  = st + ((p == 1) ? 32768 : 0);
            uint32_t bb_ = st + 65536 + ((p == 2) ? 8192 : 0);
            int rl = lane & 15;
            for (int ks = 0; ks < nst; ks++) {
                int ch = 2*ks + (lane >> 4);
                uint32_t a[4][4];
#pragma unroll
                for (int mi = 0; mi < 4; mi++) {
                    int row = wb*64 + mi*16 + rl;
                    ldsm_x4(a[mi][0], a[mi][1], a[mi][2], a[mi][3], ab + SWZ128(row*128 + ch*16));
                }
                uint32_t bf[4][2];
#pragma unroll
                for (int nj = 0; nj < 2; nj++) {
                    uint32_t r0, r1, r2, r3;
                    int row = wn*32 + nj*16 + rl;
                    ldsm_x4(r0, r1, r2, r3, bb_ + SWZ128(row*128 + ch*16));
                    bf[nj*2+0][0] = r0; bf[nj*2+0][1] = r2;
                    bf[nj*2+1][0] = r1; bf[nj*2+1][1] = r3;
                }
#pragma unroll
                for (int mi = 0; mi < 4; mi++)
#pragma unroll
                    for (int ni = 0; ni < 4; ni++)
                        mma16816(acc[mi][ni], a[mi], bf[ni][0], bf[ni][1]);
            }
        }
        __syncthreads();
    }

    // epilogue
    int g = lane >> 2, c2 = (lane & 3)*2;
#pragma unroll
    for (int mi = 0; mi < 4; mi++) {
#pragma unroll
        for (int ni = 0; ni < 4; ni++) {
            int col = n0 + wn*32 + ni*8 + c2;
            if (col < NENT) {
                size_t r0 = (size_t)(b0 + wb*64 + mi*16 + g) * NENT + col;
                size_t r1 = r0 + (size_t)8 * NENT;
                *(float2*)(out + r0) = make_float2(acc[mi][ni][0], acc[mi][ni][1]);
                *(float2*)(out + r1) = make_float2(acc[mi][ni][2], acc[mi][ni][3]);
            }
        }
    }
}

// ---------------- launch ----------------
extern "C" void kernel_launch(void* const* d_in, const int* in_sizes, int n_in,
                              void* d_out, int out_size)
{
    const int*   x   = (const int*)d_in[0];
    const float* E   = (const float*)d_in[1];
    const float* R   = (const float*)d_in[2];
    const float* RnT = (const float*)d_in[3];
    const float* T   = (const float*)d_in[4];
    const float* W   = (const float*)d_in[5];
    const float* g0  = (const float*)d_in[6];
    const float* be0 = (const float*)d_in[7];
    const float* g1  = (const float*)d_in[8];
    const float* be1 = (const float*)d_in[9];
    float* out = (float*)d_out;

    cudaFuncSetAttribute(k_splitW,    cudaFuncAttributeMaxDynamicSharedMemorySize, SPLITW_SMEM);
    cudaFuncSetAttribute(k_gemmA_mma, cudaFuncAttributeMaxDynamicSharedMemorySize, SMEM_GA);
    cudaFuncSetAttribute(k_gemmB_mma, cudaFuncAttributeMaxDynamicSharedMemorySize, SMEM_GB);

    k_gather<<<128, 256>>>(x, E, R, RnT, T);
    k_stats0<<<1, 256>>>(g0, be0);
    k_norm4<<<512, 256>>>(W);
    k_finreg<<<1, 256>>>(out);
    k_splitE<<<NENTP, 128>>>(E);
    k_splitW<<<625, 256, SPLITW_SMEM>>>(W);
    k_prepA<<<BB, 256>>>();
    k_gemmA_mma<<<dim3(16, NSPLIT), 512, SMEM_GA>>>();
    k_redhA<<<1600, 256>>>();
    k_stats1<<<200, 256>>>(g1, be1);
    k_hsplit<<<BB, 128>>>();
    k_gemmB_mma<<<dim3(1564, 8), 256, SMEM_GB>>>(out);
    cudaMemcpyAsync(out + OFF_T, T, 80000 * sizeof(float), cudaMemcpyDeviceToDevice);
}

// round 6
// speedup vs baseline: 3.9433x; 1.6286x over previous
#include <cuda_runtime.h>
#include <cuda_fp16.h>
#include <cstdint>

typedef unsigned long long ull;

#define BB    2048
#define DIMD  200
#define NENT  100000
#define NENTP 100096
#define WELEM 8000000
#define KKD   40000
#define BNEPS 1e-5f

#define OFF_PRED 0LL
#define OFF_REG  204800000LL
#define OFF_T    204800005LL

#define NSPLIT 25

// ---------------- device scratch ----------------
__device__ float g_lhs  [BB*DIMD];
__device__ float g_relt [BB*DIMD];
__device__ float g_lhsn [BB*DIMD];
__device__ float g_colp [128*2*DIMD];
__device__ float g_s4p  [128*3];
__device__ float g_scale0[DIMD];
__device__ float g_shift0[DIMD];
__device__ float g_regsums[4];
__device__ float g_n4p  [512*2];
__device__ float g_h    [BB*DIMD];
__device__ float g_scale1[DIMD];
__device__ float g_shift1[DIMD];
// fp16 operands
__device__ __half g_Ef [(size_t)NENTP*256];   // E single fp16
__device__ __half g_hhi[BB*256];              // h_n hi
__device__ __half g_hlo[BB*256];              // h_n lo
__device__ __half g_Af [(size_t)BB*KKD];      // A' single fp16
__device__ __half g_Wthi[(size_t)256*KKD];    // W^T hi
__device__ __half g_Wtlo[(size_t)256*KKD];    // W^T lo
__device__ float g_hpA[(size_t)NSPLIT*BB*256];

// ---------------- helpers ----------------
__device__ __forceinline__ uint32_t smem_u32(const void* p) {
    uint32_t a;
    asm("{ .reg .u64 t; cvta.to.shared.u64 t, %1; cvt.u32.u64 %0, t; }" : "=r"(a) : "l"(p));
    return a;
}
__device__ __forceinline__ void cp16(uint32_t dst, const void* src) {
    asm volatile("cp.async.cg.shared.global [%0], [%1], 16;" :: "r"(dst), "l"(src));
}
#define CP_COMMIT() asm volatile("cp.async.commit_group;" ::: "memory")
#define CP_WAIT(n)  asm volatile("cp.async.wait_group %0;" :: "n"(n) : "memory")

__device__ __forceinline__ void ldsm_x4(uint32_t& r0, uint32_t& r1, uint32_t& r2, uint32_t& r3, uint32_t addr) {
    asm volatile("ldmatrix.sync.aligned.m8n8.x4.shared.b16 {%0,%1,%2,%3}, [%4];"
        : "=r"(r0), "=r"(r1), "=r"(r2), "=r"(r3) : "r"(addr));
}
__device__ __forceinline__ void mma16816(float* c, const uint32_t* a, uint32_t b0, uint32_t b1) {
    asm volatile("mma.sync.aligned.m16n8k16.row.col.f32.f16.f16.f32 "
        "{%0,%1,%2,%3}, {%4,%5,%6,%7}, {%8,%9}, {%0,%1,%2,%3};"
        : "+f"(c[0]), "+f"(c[1]), "+f"(c[2]), "+f"(c[3])
        : "r"(a[0]), "r"(a[1]), "r"(a[2]), "r"(a[3]), "r"(b0), "r"(b1));
}
#define SWZ128(x) ((x) ^ (((x) >> 3) & 0x70))

__device__ __forceinline__ float blockReduce256(float v, float* red) {
    int t = threadIdx.x;
    red[t] = v; __syncthreads();
#pragma unroll
    for (int s = 128; s > 0; s >>= 1) {
        if (t < s) red[t] += red[t + s];
        __syncthreads();
    }
    float r = red[0]; __syncthreads();
    return r;
}

// ---------------- K1: gather + BN0 partials + norm4 partials ----------------
__global__ void k_gather(const int* __restrict__ x,
                         const float* __restrict__ E,
                         const float* __restrict__ R,
                         const float* __restrict__ RnT,
                         const float* __restrict__ T)
{
    __shared__ float red[256];
    int t = threadIdx.x;
    int d = t;
    float cs = 0.f, cq = 0.f, s_rt = 0.f, s_rn = 0.f, s_rh = 0.f;
    if (d < DIMD) {
#pragma unroll 4
        for (int i = 0; i < 16; i++) {
            int b = blockIdx.x * 16 + i;
            int i0 = x[b*4+0], i1 = x[b*4+1], i2 = x[b*4+2], i3 = x[b*4+3];
            float l  = E[(size_t)i0*DIMD + d];
            float rt = R[(size_t)i1*DIMD + d] * T[(size_t)i3*DIMD + d];
            float rn = RnT[(size_t)i1*DIMD + d];
            float rh = E[(size_t)i2*DIMD + d];
            g_lhs [b*DIMD + d] = l;
            g_relt[b*DIMD + d] = rt;
            cs += l; cq += l*l;
            float a = rt*rt;  s_rt += a*a;
            float bq = rn*rn; s_rn += bq*bq;
            float cc = rh*rh; s_rh += cc*cc;
        }
        g_colp[blockIdx.x*2*DIMD + d]        = cs;
        g_colp[blockIdx.x*2*DIMD + DIMD + d] = cq;
    }
    float r0 = blockReduce256(s_rt, red);
    float r1 = blockReduce256(s_rn, red);
    float r2 = blockReduce256(s_rh, red);
    if (t == 0) {
        g_s4p[blockIdx.x*3 + 0] = r0;
        g_s4p[blockIdx.x*3 + 1] = r1;
        g_s4p[blockIdx.x*3 + 2] = r2;
    }
}

// ---------------- K2: BN0 stats + reg sums ----------------
__global__ void k_stats0(const float* __restrict__ gamma0, const float* __restrict__ beta0)
{
    int t = threadIdx.x;
    if (t < DIMD) {
        float s = 0.f, sq = 0.f;
        for (int k = 0; k < 128; k++) {
            s  += g_colp[k*2*DIMD + t];
            sq += g_colp[k*2*DIMD + DIMD + t];
        }
        float mu  = s  * (1.f/2048.f);
        float var = sq * (1.f/2048.f) - mu*mu;
        float rs  = rsqrtf(var + BNEPS);
        float sc  = rs * gamma0[t];
        g_scale0[t] = sc;
        g_shift0[t] = beta0[t] - mu*sc;
    } else if (t < DIMD + 3) {
        int j = t - DIMD;
        float s = 0.f;
        for (int k = 0; k < 128; k++) s += g_s4p[k*3 + j];
        g_regsums[j + 1] = s;
    }
}

// ---------------- K3: norm4(W) + norm4(lhs_n), materialize lhs_n ----------------
__global__ void k_norm4(const float* __restrict__ W)
{
    __shared__ float red[256];
    int t = threadIdx.x;
    float pw = 0.f, pl = 0.f;
    const int TOT = WELEM + BB*DIMD;
    for (int idx = blockIdx.x*256 + t; idx < TOT; idx += 512*256) {
        if (idx < WELEM) {
            float v = W[idx]; float v2 = v*v; pw += v2*v2;
        } else {
            int i = idx - WELEM;
            int d = i % DIMD;
            float v = g_lhs[i] * g_scale0[d] + g_shift0[d];
            g_lhsn[i] = v;
            float v2 = v*v; pl += v2*v2;
        }
    }
    float rl = blockReduce256(pl, red);
    float rw = blockReduce256(pw, red);
    if (t == 0) {
        g_n4p[blockIdx.x*2 + 0] = rl;
        g_n4p[blockIdx.x*2 + 1] = rw;
    }
}

// ---------------- K4: write reg[5] ----------------
__global__ void k_finreg(float* __restrict__ out)
{
    __shared__ float red[256];
    int t = threadIdx.x;
    float a = 0.f, b = 0.f;
    for (int i = t; i < 512; i += 256) { a += g_n4p[2*i]; b += g_n4p[2*i + 1]; }
    float sl = blockReduce256(a, red);
    float sw = blockReduce256(b, red);
    if (t == 0) {
        out[OFF_REG + 0] = powf(sl,           0.25f);
        out[OFF_REG + 1] = powf(g_regsums[1], 0.25f);
        out[OFF_REG + 2] = powf(g_regsums[2], 0.25f);
        out[OFF_REG + 3] = powf(g_regsums[3], 0.25f);
        out[OFF_REG + 4] = powf(sw,           0.25f);
    }
}

// ---------------- K5a: build A' = relt (x) lhsn, single fp16 ----------------
__global__ void k_prepA()
{
    __shared__ float sr[DIMD], sl[DIMD];
    int b = blockIdx.x, t = threadIdx.x;
    if (t < DIMD) { sr[t] = g_relt[b*DIMD + t]; sl[t] = g_lhsn[b*DIMD + t]; }
    __syncthreads();
    size_t rowo = (size_t)b * KKD;
    for (int i2 = 2*t; i2 < KKD; i2 += 512) {
        int k = i2 / DIMD, d = i2 - k*DIMD;   // DIMD even -> pair never straddles k
        float a0 = sr[k]*sl[d];
        float a1 = sr[k]*sl[d+1];
        *(__half2*)&g_Af[rowo + i2] = __floats2half2_rn(a0, a1);
    }
}

// ---------------- K5b: W -> Wt (transposed, fp16 hi/lo, e padded to 256) ----------------
#define SPLITW_SMEM (64*DIMD*4)
__global__ void k_splitW(const float* __restrict__ W)
{
    extern __shared__ char swraw[];
    float* sm = (float*)swraw;      // 64 x 200
    int t = threadIdx.x;
    int kd0 = blockIdx.x * 64;
    for (int i = t; i < 64*DIMD; i += 256)
        sm[i] = W[(size_t)kd0*DIMD + i];
    __syncthreads();
    for (int idx = t; idx < 256*64; idx += 256) {
        int e = idx >> 6, kd = idx & 63;
        float v = (e < DIMD) ? sm[kd*DIMD + e] : 0.f;
        __half h = __float2half_rn(v);
        g_Wthi[(size_t)e*KKD + kd0 + kd] = h;
        g_Wtlo[(size_t)e*KKD + kd0 + kd] = __float2half_rn(v - __half2float(h));
    }
}

// ---------------- K5c: GEMM-A via mma.sync fp16 (2-pass: A*Whi + A*Wlo) ----------------
// CTA: 128 b x 256 n(e, padded), K-slice 1600 (25 chunks of 64), 512 thr.
// 16 warps = 4b x 4n; warp 32b x 64n.
#define GA_STG 81920
#define SMEM_GA (2*GA_STG + 1024)
__global__ void __launch_bounds__(512, 1) k_gemmA_mma()
{
    extern __shared__ char smrawA[];
    uint32_t base = (smem_u32(smrawA) + 1023) & ~1023u;

    int t = threadIdx.x;
    int lane = t & 31, wid = t >> 5;
    int wb = wid >> 2, wn = wid & 3;
    int b0  = blockIdx.x * 128;
    int kd0 = blockIdx.y * 1600;

    float acc[2][8][4];
#pragma unroll
    for (int i = 0; i < 2; i++)
#pragma unroll
        for (int j = 0; j < 8; j++)
#pragma unroll
            for (int q = 0; q < 4; q++) acc[i][j][q] = 0.f;

    // prefetch chunk 0: A @0 (16KB), Whi @16384 (32KB), Wlo @49152 (32KB)
    {
        uint32_t st = base;
#pragma unroll
        for (int j = 0; j < 2; j++) {
            int idx = t + 512*j;
            int row = idx >> 3, seg = idx & 7;
            cp16(st + SWZ128(row*128 + seg*16), g_Af + (size_t)(b0 + row)*KKD + kd0 + seg*8);
        }
#pragma unroll
        for (int j = 0; j < 4; j++) {
            int idx = t + 512*j;
            int row = idx >> 3, seg = idx & 7;
            size_t src = (size_t)row*KKD + kd0 + seg*8;
            cp16(st + 16384 + SWZ128(row*128 + seg*16), g_Wthi + src);
            cp16(st + 49152 + SWZ128(row*128 + seg*16), g_Wtlo + src);
        }
        CP_COMMIT();
    }

    for (int c = 0; c < 25; c++) {
        if (c + 1 < 25) {
            int kc = (c+1)*64;
            uint32_t st = base + ((c+1)&1)*GA_STG;
#pragma unroll
            for (int j = 0; j < 2; j++) {
                int idx = t + 512*j;
                int row = idx >> 3, seg = idx & 7;
                cp16(st + SWZ128(row*128 + seg*16), g_Af + (size_t)(b0 + row)*KKD + kd0 + kc + seg*8);
            }
#pragma unroll
            for (int j = 0; j < 4; j++) {
                int idx = t + 512*j;
                int row = idx >> 3, seg = idx & 7;
                size_t src = (size_t)row*KKD + kd0 + kc + seg*8;
                cp16(st + 16384 + SWZ128(row*128 + seg*16), g_Wthi + src);
                cp16(st + 49152 + SWZ128(row*128 + seg*16), g_Wtlo + src);
            }
            CP_COMMIT();
            CP_WAIT(1);
        } else {
            CP_WAIT(0);
        }
        __syncthreads();

        uint32_t st = base + (c&1)*GA_STG;
        int rl = lane & 15;
        for (int ks = 0; ks < 4; ks++) {
            int ch = 2*ks + (lane >> 4);
            uint32_t a[2][4];
#pragma unroll
            for (int mi = 0; mi < 2; mi++) {
                int row = wb*32 + mi*16 + rl;
                ldsm_x4(a[mi][0], a[mi][1], a[mi][2], a[mi][3], st + SWZ128(row*128 + ch*16));
            }
#pragma unroll
            for (int p = 0; p < 2; p++) {
                uint32_t bb_ = st + 16384 + p*32768;
                uint32_t bf[8][2];
#pragma unroll
                for (int nj = 0; nj < 4; nj++) {
                    uint32_t r0, r1, r2, r3;
                    int row = wn*64 + nj*16 + rl;
                    ldsm_x4(r0, r1, r2, r3, bb_ + SWZ128(row*128 + ch*16));
                    bf[nj*2+0][0] = r0; bf[nj*2+0][1] = r2;
                    bf[nj*2+1][0] = r1; bf[nj*2+1][1] = r3;
                }
#pragma unroll
                for (int mi = 0; mi < 2; mi++)
#pragma unroll
                    for (int ni = 0; ni < 8; ni++)
                        mma16816(acc[mi][ni], a[mi], bf[ni][0], bf[ni][1]);
            }
        }
        __syncthreads();
    }

    float* dst = g_hpA + (size_t)blockIdx.y * (BB*256);
    int g = lane >> 2, c2 = (lane & 3)*2;
#pragma unroll
    for (int mi = 0; mi < 2; mi++) {
#pragma unroll
        for (int ni = 0; ni < 8; ni++) {
            int col = wn*64 + ni*8 + c2;
            if (col < DIMD) {
                size_t r0 = (size_t)(b0 + wb*32 + mi*16 + g) * 256 + col;
                *(float2*)(dst + r0)         = make_float2(acc[mi][ni][0], acc[mi][ni][1]);
                *(float2*)(dst + r0 + 8*256) = make_float2(acc[mi][ni][2], acc[mi][ni][3]);
            }
        }
    }
}

// ---------------- K6: reduce k-split partials ----------------
__global__ void k_redhA()
{
    int i = blockIdx.x*256 + threadIdx.x;
    if (i < BB*DIMD) {
        int b = i / DIMD, n = i - b*DIMD;
        float s = 0.f;
#pragma unroll
        for (int ks = 0; ks < NSPLIT; ks++)
            s += g_hpA[(size_t)ks*(BB*256) + (size_t)b*256 + n];
        g_h[i] = s;
    }
}

// ---------------- K7: BN1 stats ----------------
__global__ void k_stats1(const float* __restrict__ gamma1, const float* __restrict__ beta1)
{
    __shared__ float r0[256];
    int e = blockIdx.x, t = threadIdx.x;
    float s = 0.f, sq = 0.f;
    for (int b = t; b < BB; b += 256) {
        float v = g_h[b*DIMD + e];
        s += v; sq += v*v;
    }
    float ts = blockReduce256(s, r0);
    float tq = blockReduce256(sq, r0);
    if (t == 0) {
        float mu  = ts * (1.f/2048.f);
        float var = tq * (1.f/2048.f) - mu*mu;
        float rs  = rsqrtf(var + BNEPS);
        float sc  = rs * gamma1[e];
        g_scale1[e] = sc;
        g_shift1[e] = beta1[e] - mu*sc;
    }
}

// ---------------- K8a: E -> fp16 single (padded) ----------------
__global__ void k_splitE(const float* __restrict__ E)
{
    int r = blockIdx.x;
    int c = threadIdx.x * 2;
    float v0 = 0.f, v1 = 0.f;
    if (r < NENT) {
        if (c < DIMD)     v0 = E[(size_t)r*DIMD + c];
        if (c + 1 < DIMD) v1 = E[(size_t)r*DIMD + c + 1];
    }
    *(__half2*)&g_Ef[(size_t)r*256 + c] = __floats2half2_rn(v0, v1);
}

// ---------------- K8b: BN1 apply + split h_n into fp16 hi/lo ----------------
__global__ void k_hsplit()
{
    int b = blockIdx.x;
    int c = threadIdx.x * 2;
    float v0 = 0.f, v1 = 0.f;
    if (c < DIMD)     v0 = g_h[b*DIMD + c]     * g_scale1[c]     + g_shift1[c];
    if (c + 1 < DIMD) v1 = g_h[b*DIMD + c + 1] * g_scale1[c + 1] + g_shift1[c + 1];
    __half h0 = __float2half_rn(v0);
    __half h1 = __float2half_rn(v1);
    __half l0 = __float2half_rn(v0 - __half2float(h0));
    __half l1 = __float2half_rn(v1 - __half2float(h1));
    size_t o = (size_t)b*256 + c;
    *(__half2*)&g_hhi[o] = __half2(h0, h1);
    *(__half2*)&g_hlo[o] = __half2(l0, l1);
}

// ---------------- K9: GEMM-B via mma.sync fp16 (2-pass: hhi*E + hlo*E) ----------------
// CTA: 256 b x 128 n. 8 warps = 4(b) x 2(n); warp 64b x 64n.
// 4 K-chunks of 64. Ahi @0 (32KB), Alo @32768, E @65536 (16KB).
#define GB_STG 81920
#define SMEM_GB (2*GB_STG + 1024)
__global__ void __launch_bounds__(256, 1) k_gemmB_mma(float* __restrict__ out)
{
    extern __shared__ char smrawB[];
    uint32_t base = (smem_u32(smrawB) + 1023) & ~1023u;

    int t = threadIdx.x;
    int lane = t & 31, wid = t >> 5;
    int wb = wid >> 1, wn = wid & 1;
    int n0 = blockIdx.x * 128;
    int b0 = blockIdx.y * 256;

    float acc[4][8][4];
#pragma unroll
    for (int i = 0; i < 4; i++)
#pragma unroll
        for (int j = 0; j < 8; j++)
#pragma unroll
            for (int q = 0; q < 4; q++) acc[i][j][q] = 0.f;

    // prefetch chunk 0
    {
        uint32_t st = base;
#pragma unroll
        for (int j = 0; j < 8; j++) {
            int idx = t + 256*j;
            int row = idx >> 3, seg = idx & 7;
            size_t src = (size_t)(b0 + row)*256 + seg*8;
            cp16(st +         SWZ128(row*128 + seg*16), g_hhi + src);
            cp16(st + 32768 + SWZ128(row*128 + seg*16), g_hlo + src);
        }
#pragma unroll
        for (int j = 0; j < 4; j++) {
            int idx = t + 256*j;
            int row = idx >> 3, seg = idx & 7;
            cp16(st + 65536 + SWZ128(row*128 + seg*16), g_Ef + (size_t)(n0 + row)*256 + seg*8);
        }
        CP_COMMIT();
    }

    for (int c = 0; c < 4; c++) {
        if (c + 1 < 4) {
            int kc = (c+1)*64;
            uint32_t st = base + ((c+1)&1)*GB_STG;
#pragma unroll
            for (int j = 0; j < 8; j++) {
                int idx = t + 256*j;
                int row = idx >> 3, seg = idx & 7;
                size_t src = (size_t)(b0 + row)*256 + kc + seg*8;
                cp16(st +         SWZ128(row*128 + seg*16), g_hhi + src);
                cp16(st + 32768 + SWZ128(row*128 + seg*16), g_hlo + src);
            }
#pragma unroll
            for (int j = 0; j < 4; j++) {
                int idx = t + 256*j;
                int row = idx >> 3, seg = idx & 7;
                cp16(st + 65536 + SWZ128(row*128 + seg*16), g_Ef + (size_t)(n0 + row)*256 + kc + seg*8);
            }
            CP_COMMIT();
            CP_WAIT(1);
        } else {
            CP_WAIT(0);
        }
        __syncthreads();

        uint32_t st = base + (c&1)*GB_STG;
        int nst = (c == 3) ? 1 : 4;   // k >= 208 is zero padding
        int rl = lane & 15;
        for (int ks = 0; ks < nst; ks++) {
            int ch = 2*ks + (lane >> 4);
            uint32_t bf[8][2];
#pragma unroll
            for (int nj = 0; nj < 4; nj++) {
                uint32_t r0, r1, r2, r3;
                int row = wn*64 + nj*16 + rl;
                ldsm_x4(r0, r1, r2, r3, st + 65536 + SWZ128(row*128 + ch*16));
                bf[nj*2+0][0] = r0; bf[nj*2+0][1] = r2;
                bf[nj*2+1][0] = r1; bf[nj*2+1][1] = r3;
            }
#pragma unroll
            for (int p = 0; p < 2; p++) {
                uint32_t ab = st + p*32768;
                uint32_t a[4][4];
#pragma unroll
                for (int mi = 0; mi < 4; mi++) {
                    int row = wb*64 + mi*16 + rl;
                    ldsm_x4(a[mi][0], a[mi][1], a[mi][2], a[mi][3], ab + SWZ128(row*128 + ch*16));
                }
#pragma unroll
                for (int mi = 0; mi < 4; mi++)
#pragma unroll
                    for (int ni = 0; ni < 8; ni++)
                        mma16816(acc[mi][ni], a[mi], bf[ni][0], bf[ni][1]);
            }
        }
        __syncthreads();
    }

    // epilogue
    int g = lane >> 2, c2 = (lane & 3)*2;
#pragma unroll
    for (int mi = 0; mi < 4; mi++) {
#pragma unroll
        for (int ni = 0; ni < 8; ni++) {
            int col = n0 + wn*64 + ni*8 + c2;
            if (col < NENT) {
                size_t r0 = (size_t)(b0 + wb*64 + mi*16 + g) * NENT + col;
                size_t r1 = r0 + (size_t)8 * NENT;
                *(float2*)(out + r0) = make_float2(acc[mi][ni][0], acc[mi][ni][1]);
                *(float2*)(out + r1) = make_float2(acc[mi][ni][2], acc[mi][ni][3]);
            }
        }
    }
}

// ---------------- launch ----------------
extern "C" void kernel_launch(void* const* d_in, const int* in_sizes, int n_in,
                              void* d_out, int out_size)
{
    const int*   x   = (const int*)d_in[0];
    const float* E   = (const float*)d_in[1];
    const float* R   = (const float*)d_in[2];
    const float* RnT = (const float*)d_in[3];
    const float* T   = (const float*)d_in[4];
    const float* W   = (const float*)d_in[5];
    const float* g0  = (const float*)d_in[6];
    const float* be0 = (const float*)d_in[7];
    const float* g1  = (const float*)d_in[8];
    const float* be1 = (const float*)d_in[9];
    float* out = (float*)d_out;

    cudaFuncSetAttribute(k_splitW,    cudaFuncAttributeMaxDynamicSharedMemorySize, SPLITW_SMEM);
    cudaFuncSetAttribute(k_gemmA_mma, cudaFuncAttributeMaxDynamicSharedMemorySize, SMEM_GA);
    cudaFuncSetAttribute(k_gemmB_mma, cudaFuncAttributeMaxDynamicSharedMemorySize, SMEM_GB);

    k_gather<<<128, 256>>>(x, E, R, RnT, T);
    k_stats0<<<1, 256>>>(g0, be0);
    k_norm4<<<512, 256>>>(W);
    k_finreg<<<1, 256>>>(out);
    k_splitE<<<NENTP, 128>>>(E);
    k_splitW<<<625, 256, SPLITW_SMEM>>>(W);
    k_prepA<<<BB, 256>>>();
    k_gemmA_mma<<<dim3(16, NSPLIT), 512, SMEM_GA>>>();
    k_redhA<<<1600, 256>>>();
    k_stats1<<<200, 256>>>(g1, be1);
    k_hsplit<<<BB, 128>>>();
    k_gemmB_mma<<<dim3(782, 8), 256, SMEM_GB>>>(out);
    cudaMemcpyAsync(out + OFF_T, T, 80000 * sizeof(float), cudaMemcpyDeviceToDevice);
}

// round 7
// speedup vs baseline: 4.8178x; 1.2218x over previous
#include <cuda_runtime.h>
#include <cuda_fp16.h>
#include <cstdint>

typedef unsigned long long ull;

#define BB    2048
#define DIMD  200
#define NENT  100000
#define NENTP 100096
#define WELEM 8000000
#define KKD   40000
#define BNEPS 1e-5f

#define OFF_PRED 0LL
#define OFF_REG  204800000LL
#define OFF_T    204800005LL

#define NSPLIT 25

// ---------------- device scratch ----------------
__device__ float g_lhs  [BB*DIMD];
__device__ float g_relt [BB*DIMD];
__device__ float g_lhsn [BB*DIMD];
__device__ float g_colp [128*2*DIMD];
__device__ float g_s4p  [128*3];
__device__ float g_scale0[DIMD];
__device__ float g_shift0[DIMD];
__device__ float g_regsums[4];
__device__ float g_n4p  [512*2];
__device__ float g_h    [BB*DIMD];
__device__ float g_scale1[DIMD];
__device__ float g_shift1[DIMD];
// fp16 operands
__device__ __half g_Ef [(size_t)NENTP*256];   // E single fp16
__device__ __half g_hf [BB*256];              // h_n single fp16
__device__ __half g_Af [(size_t)BB*KKD];      // A' single fp16
__device__ __half g_Wthi[(size_t)256*KKD];    // W^T hi
__device__ __half g_Wtlo[(size_t)256*KKD];    // W^T lo
__device__ float g_hpA[(size_t)NSPLIT*BB*256];

// ---------------- helpers ----------------
__device__ __forceinline__ uint32_t smem_u32(const void* p) {
    uint32_t a;
    asm("{ .reg .u64 t; cvta.to.shared.u64 t, %1; cvt.u32.u64 %0, t; }" : "=r"(a) : "l"(p));
    return a;
}
__device__ __forceinline__ void cp16(uint32_t dst, const void* src) {
    asm volatile("cp.async.cg.shared.global [%0], [%1], 16;" :: "r"(dst), "l"(src));
}
#define CP_COMMIT() asm volatile("cp.async.commit_group;" ::: "memory")
#define CP_WAIT(n)  asm volatile("cp.async.wait_group %0;" :: "n"(n) : "memory")

__device__ __forceinline__ void ldsm_x4(uint32_t& r0, uint32_t& r1, uint32_t& r2, uint32_t& r3, uint32_t addr) {
    asm volatile("ldmatrix.sync.aligned.m8n8.x4.shared.b16 {%0,%1,%2,%3}, [%4];"
        : "=r"(r0), "=r"(r1), "=r"(r2), "=r"(r3) : "r"(addr));
}
__device__ __forceinline__ void mma16816(float* c, const uint32_t* a, uint32_t b0, uint32_t b1) {
    asm volatile("mma.sync.aligned.m16n8k16.row.col.f32.f16.f16.f32 "
        "{%0,%1,%2,%3}, {%4,%5,%6,%7}, {%8,%9}, {%0,%1,%2,%3};"
        : "+f"(c[0]), "+f"(c[1]), "+f"(c[2]), "+f"(c[3])
        : "r"(a[0]), "r"(a[1]), "r"(a[2]), "r"(a[3]), "r"(b0), "r"(b1));
}
#define SWZ128(x) ((x) ^ (((x) >> 3) & 0x70))

__device__ __forceinline__ float blockReduce256(float v, float* red) {
    int t = threadIdx.x;
    red[t] = v; __syncthreads();
#pragma unroll
    for (int s = 128; s > 0; s >>= 1) {
        if (t < s) red[t] += red[t + s];
        __syncthreads();
    }
    float r = red[0]; __syncthreads();
    return r;
}

// ---------------- K1: gather + BN0 partials + norm4 partials ----------------
__global__ void k_gather(const int* __restrict__ x,
                         const float* __restrict__ E,
                         const float* __restrict__ R,
                         const float* __restrict__ RnT,
                         const float* __restrict__ T)
{
    __shared__ float red[256];
    int t = threadIdx.x;
    int d = t;
    float cs = 0.f, cq = 0.f, s_rt = 0.f, s_rn = 0.f, s_rh = 0.f;
    if (d < DIMD) {
#pragma unroll 4
        for (int i = 0; i < 16; i++) {
            int b = blockIdx.x * 16 + i;
            int i0 = x[b*4+0], i1 = x[b*4+1], i2 = x[b*4+2], i3 = x[b*4+3];
            float l  = E[(size_t)i0*DIMD + d];
            float rt = R[(size_t)i1*DIMD + d] * T[(size_t)i3*DIMD + d];
            float rn = RnT[(size_t)i1*DIMD + d];
            float rh = E[(size_t)i2*DIMD + d];
            g_lhs [b*DIMD + d] = l;
            g_relt[b*DIMD + d] = rt;
            cs += l; cq += l*l;
            float a = rt*rt;  s_rt += a*a;
            float bq = rn*rn; s_rn += bq*bq;
            float cc = rh*rh; s_rh += cc*cc;
        }
        g_colp[blockIdx.x*2*DIMD + d]        = cs;
        g_colp[blockIdx.x*2*DIMD + DIMD + d] = cq;
    }
    float r0 = blockReduce256(s_rt, red);
    float r1 = blockReduce256(s_rn, red);
    float r2 = blockReduce256(s_rh, red);
    if (t == 0) {
        g_s4p[blockIdx.x*3 + 0] = r0;
        g_s4p[blockIdx.x*3 + 1] = r1;
        g_s4p[blockIdx.x*3 + 2] = r2;
    }
}

// ---------------- K2: BN0 stats + reg sums ----------------
__global__ void k_stats0(const float* __restrict__ gamma0, const float* __restrict__ beta0)
{
    int t = threadIdx.x;
    if (t < DIMD) {
        float s = 0.f, sq = 0.f;
        for (int k = 0; k < 128; k++) {
            s  += g_colp[k*2*DIMD + t];
            sq += g_colp[k*2*DIMD + DIMD + t];
        }
        float mu  = s  * (1.f/2048.f);
        float var = sq * (1.f/2048.f) - mu*mu;
        float rs  = rsqrtf(var + BNEPS);
        float sc  = rs * gamma0[t];
        g_scale0[t] = sc;
        g_shift0[t] = beta0[t] - mu*sc;
    } else if (t < DIMD + 3) {
        int j = t - DIMD;
        float s = 0.f;
        for (int k = 0; k < 128; k++) s += g_s4p[k*3 + j];
        g_regsums[j + 1] = s;
    }
}

// ---------------- K3: norm4(W) + norm4(lhs_n), materialize lhs_n ----------------
__global__ void k_norm4(const float* __restrict__ W)
{
    __shared__ float red[256];
    int t = threadIdx.x;
    float pw = 0.f, pl = 0.f;
    const int TOT = WELEM + BB*DIMD;
    for (int idx = blockIdx.x*256 + t; idx < TOT; idx += 512*256) {
        if (idx < WELEM) {
            float v = W[idx]; float v2 = v*v; pw += v2*v2;
        } else {
            int i = idx - WELEM;
            int d = i % DIMD;
            float v = g_lhs[i] * g_scale0[d] + g_shift0[d];
            g_lhsn[i] = v;
            float v2 = v*v; pl += v2*v2;
        }
    }
    float rl = blockReduce256(pl, red);
    float rw = blockReduce256(pw, red);
    if (t == 0) {
        g_n4p[blockIdx.x*2 + 0] = rl;
        g_n4p[blockIdx.x*2 + 1] = rw;
    }
}

// ---------------- K4: write reg[5] ----------------
__global__ void k_finreg(float* __restrict__ out)
{
    __shared__ float red[256];
    int t = threadIdx.x;
    float a = 0.f, b = 0.f;
    for (int i = t; i < 512; i += 256) { a += g_n4p[2*i]; b += g_n4p[2*i + 1]; }
    float sl = blockReduce256(a, red);
    float sw = blockReduce256(b, red);
    if (t == 0) {
        out[OFF_REG + 0] = powf(sl,           0.25f);
        out[OFF_REG + 1] = powf(g_regsums[1], 0.25f);
        out[OFF_REG + 2] = powf(g_regsums[2], 0.25f);
        out[OFF_REG + 3] = powf(g_regsums[3], 0.25f);
        out[OFF_REG + 4] = powf(sw,           0.25f);
    }
}

// ---------------- K5a: build A' = relt (x) lhsn, single fp16 ----------------
__global__ void k_prepA()
{
    __shared__ float sr[DIMD], sl[DIMD];
    int b = blockIdx.x, t = threadIdx.x;
    if (t < DIMD) { sr[t] = g_relt[b*DIMD + t]; sl[t] = g_lhsn[b*DIMD + t]; }
    __syncthreads();
    size_t rowo = (size_t)b * KKD;
    for (int i2 = 2*t; i2 < KKD; i2 += 512) {
        int k = i2 / DIMD, d = i2 - k*DIMD;   // DIMD even -> pair never straddles k
        float a0 = sr[k]*sl[d];
        float a1 = sr[k]*sl[d+1];
        *(__half2*)&g_Af[rowo + i2] = __floats2half2_rn(a0, a1);
    }
}

// ---------------- K5b: W -> Wt (transposed, fp16 hi/lo, e padded to 256) ----------------
#define SPLITW_SMEM (64*DIMD*4)
__global__ void k_splitW(const float* __restrict__ W)
{
    extern __shared__ char swraw[];
    float* sm = (float*)swraw;      // 64 x 200
    int t = threadIdx.x;
    int kd0 = blockIdx.x * 64;
    for (int i = t; i < 64*DIMD; i += 256)
        sm[i] = W[(size_t)kd0*DIMD + i];
    __syncthreads();
    for (int idx = t; idx < 256*64; idx += 256) {
        int e = idx >> 6, kd = idx & 63;
        float v = (e < DIMD) ? sm[kd*DIMD + e] : 0.f;
        __half h = __float2half_rn(v);
        g_Wthi[(size_t)e*KKD + kd0 + kd] = h;
        g_Wtlo[(size_t)e*KKD + kd0 + kd] = __float2half_rn(v - __half2float(h));
    }
}

// ---------------- K5c: GEMM-A via mma.sync fp16 (2-pass: A*Whi + A*Wlo) ----------------
// CTA: 128 b x 256 n(e, padded), K-slice 1600 (25 chunks of 64), 512 thr.
// 16 warps = 4b x 4n; warp 32b x 64n.
#define GA_STG 81920
#define SMEM_GA (2*GA_STG + 1024)
__global__ void __launch_bounds__(512, 1) k_gemmA_mma()
{
    extern __shared__ char smrawA[];
    uint32_t base = (smem_u32(smrawA) + 1023) & ~1023u;

    int t = threadIdx.x;
    int lane = t & 31, wid = t >> 5;
    int wb = wid >> 2, wn = wid & 3;
    int b0  = blockIdx.x * 128;
    int kd0 = blockIdx.y * 1600;

    float acc[2][8][4];
#pragma unroll
    for (int i = 0; i < 2; i++)
#pragma unroll
        for (int j = 0; j < 8; j++)
#pragma unroll
            for (int q = 0; q < 4; q++) acc[i][j][q] = 0.f;

    // prefetch chunk 0: A @0 (16KB), Whi @16384 (32KB), Wlo @49152 (32KB)
    {
        uint32_t st = base;
#pragma unroll
        for (int j = 0; j < 2; j++) {
            int idx = t + 512*j;
            int row = idx >> 3, seg = idx & 7;
            cp16(st + SWZ128(row*128 + seg*16), g_Af + (size_t)(b0 + row)*KKD + kd0 + seg*8);
        }
#pragma unroll
        for (int j = 0; j < 4; j++) {
            int idx = t + 512*j;
            int row = idx >> 3, seg = idx & 7;
            size_t src = (size_t)row*KKD + kd0 + seg*8;
            cp16(st + 16384 + SWZ128(row*128 + seg*16), g_Wthi + src);
            cp16(st + 49152 + SWZ128(row*128 + seg*16), g_Wtlo + src);
        }
        CP_COMMIT();
    }

    for (int c = 0; c < 25; c++) {
        if (c + 1 < 25) {
            int kc = (c+1)*64;
            uint32_t st = base + ((c+1)&1)*GA_STG;
#pragma unroll
            for (int j = 0; j < 2; j++) {
                int idx = t + 512*j;
                int row = idx >> 3, seg = idx & 7;
                cp16(st + SWZ128(row*128 + seg*16), g_Af + (size_t)(b0 + row)*KKD + kd0 + kc + seg*8);
            }
#pragma unroll
            for (int j = 0; j < 4; j++) {
                int idx = t + 512*j;
                int row = idx >> 3, seg = idx & 7;
                size_t src = (size_t)row*KKD + kd0 + kc + seg*8;
                cp16(st + 16384 + SWZ128(row*128 + seg*16), g_Wthi + src);
                cp16(st + 49152 + SWZ128(row*128 + seg*16), g_Wtlo + src);
            }
            CP_COMMIT();
            CP_WAIT(1);
        } else {
            CP_WAIT(0);
        }
        __syncthreads();

        uint32_t st = base + (c&1)*GA_STG;
        int rl = lane & 15;
        for (int ks = 0; ks < 4; ks++) {
            int ch = 2*ks + (lane >> 4);
            uint32_t a[2][4];
#pragma unroll
            for (int mi = 0; mi < 2; mi++) {
                int row = wb*32 + mi*16 + rl;
                ldsm_x4(a[mi][0], a[mi][1], a[mi][2], a[mi][3], st + SWZ128(row*128 + ch*16));
            }
#pragma unroll
            for (int p = 0; p < 2; p++) {
                uint32_t bb_ = st + 16384 + p*32768;
                uint32_t bf[8][2];
#pragma unroll
                for (int nj = 0; nj < 4; nj++) {
                    uint32_t r0, r1, r2, r3;
                    int row = wn*64 + nj*16 + rl;
                    ldsm_x4(r0, r1, r2, r3, bb_ + SWZ128(row*128 + ch*16));
                    bf[nj*2+0][0] = r0; bf[nj*2+0][1] = r2;
                    bf[nj*2+1][0] = r1; bf[nj*2+1][1] = r3;
                }
#pragma unroll
                for (int mi = 0; mi < 2; mi++)
#pragma unroll
                    for (int ni = 0; ni < 8; ni++)
                        mma16816(acc[mi][ni], a[mi], bf[ni][0], bf[ni][1]);
            }
        }
        __syncthreads();
    }

    float* dst = g_hpA + (size_t)blockIdx.y * (BB*256);
    int g = lane >> 2, c2 = (lane & 3)*2;
#pragma unroll
    for (int mi = 0; mi < 2; mi++) {
#pragma unroll
        for (int ni = 0; ni < 8; ni++) {
            int col = wn*64 + ni*8 + c2;
            if (col < DIMD) {
                size_t r0 = (size_t)(b0 + wb*32 + mi*16 + g) * 256 + col;
                *(float2*)(dst + r0)         = make_float2(acc[mi][ni][0], acc[mi][ni][1]);
                *(float2*)(dst + r0 + 8*256) = make_float2(acc[mi][ni][2], acc[mi][ni][3]);
            }
        }
    }
}

// ---------------- K6: reduce k-split partials ----------------
__global__ void k_redhA()
{
    int i = blockIdx.x*256 + threadIdx.x;
    if (i < BB*DIMD) {
        int b = i / DIMD, n = i - b*DIMD;
        float s = 0.f;
#pragma unroll
        for (int ks = 0; ks < NSPLIT; ks++)
            s += g_hpA[(size_t)ks*(BB*256) + (size_t)b*256 + n];
        g_h[i] = s;
    }
}

// ---------------- K7: BN1 stats ----------------
__global__ void k_stats1(const float* __restrict__ gamma1, const float* __restrict__ beta1)
{
    __shared__ float r0[256];
    int e = blockIdx.x, t = threadIdx.x;
    float s = 0.f, sq = 0.f;
    for (int b = t; b < BB; b += 256) {
        float v = g_h[b*DIMD + e];
        s += v; sq += v*v;
    }
    float ts = blockReduce256(s, r0);
    float tq = blockReduce256(sq, r0);
    if (t == 0) {
        float mu  = ts * (1.f/2048.f);
        float var = tq * (1.f/2048.f) - mu*mu;
        float rs  = rsqrtf(var + BNEPS);
        float sc  = rs * gamma1[e];
        g_scale1[e] = sc;
        g_shift1[e] = beta1[e] - mu*sc;
    }
}

// ---------------- K8a: E -> fp16 single (padded) ----------------
__global__ void k_splitE(const float* __restrict__ E)
{
    int r = blockIdx.x;
    int c = threadIdx.x * 2;
    float v0 = 0.f, v1 = 0.f;
    if (r < NENT) {
        if (c < DIMD)     v0 = E[(size_t)r*DIMD + c];
        if (c + 1 < DIMD) v1 = E[(size_t)r*DIMD + c + 1];
    }
    *(__half2*)&g_Ef[(size_t)r*256 + c] = __floats2half2_rn(v0, v1);
}

// ---------------- K8b: BN1 apply, h_n -> single fp16 ----------------
__global__ void k_hconv()
{
    int b = blockIdx.x;
    int c = threadIdx.x * 2;
    float v0 = 0.f, v1 = 0.f;
    if (c < DIMD)     v0 = g_h[b*DIMD + c]     * g_scale1[c]     + g_shift1[c];
    if (c + 1 < DIMD) v1 = g_h[b*DIMD + c + 1] * g_scale1[c + 1] + g_shift1[c + 1];
    *(__half2*)&g_hf[(size_t)b*256 + c] = __floats2half2_rn(v0, v1);
}

// ---------------- K9: GEMM-B via mma.sync fp16, single pass ----------------
// CTA: 256 b x 128 n, 512 thr. 16 warps = 4b x 4n; warp 64b x 32n.
// 4 K-chunks of 64. h @0 (32KB), E @32768 (16KB). b fastest in grid -> E L2 reuse.
#define GB_STG 49152
#define SMEM_GB (2*GB_STG + 1024)
__global__ void __launch_bounds__(512, 1) k_gemmB_mma(float* __restrict__ out)
{
    extern __shared__ char smrawB[];
    uint32_t base = (smem_u32(smrawB) + 1023) & ~1023u;

    int t = threadIdx.x;
    int lane = t & 31, wid = t >> 5;
    int wb = wid >> 2, wn = wid & 3;
    int b0 = blockIdx.x * 256;   // 8 values, fastest -> concurrent CTAs share E tile
    int n0 = blockIdx.y * 128;

    float acc[4][4][4];
#pragma unroll
    for (int i = 0; i < 4; i++)
#pragma unroll
        for (int j = 0; j < 4; j++)
#pragma unroll
            for (int q = 0; q < 4; q++) acc[i][j][q] = 0.f;

    // prefetch chunk 0
    {
        uint32_t st = base;
#pragma unroll
        for (int j = 0; j < 4; j++) {
            int idx = t + 512*j;
            int row = idx >> 3, seg = idx & 7;
            cp16(st + SWZ128(row*128 + seg*16), g_hf + (size_t)(b0 + row)*256 + seg*8);
        }
#pragma unroll
        for (int j = 0; j < 2; j++) {
            int idx = t + 512*j;
            int row = idx >> 3, seg = idx & 7;
            cp16(st + 32768 + SWZ128(row*128 + seg*16), g_Ef + (size_t)(n0 + row)*256 + seg*8);
        }
        CP_COMMIT();
    }

    for (int c = 0; c < 4; c++) {
        if (c + 1 < 4) {
            int kc = (c+1)*64;
            uint32_t st = base + ((c+1)&1)*GB_STG;
#pragma unroll
            for (int j = 0; j < 4; j++) {
                int idx = t + 512*j;
                int row = idx >> 3, seg = idx & 7;
                cp16(st + SWZ128(row*128 + seg*16), g_hf + (size_t)(b0 + row)*256 + kc + seg*8);
            }
#pragma unroll
            for (int j = 0; j < 2; j++) {
                int idx = t + 512*j;
                int row = idx >> 3, seg = idx & 7;
                cp16(st + 32768 + SWZ128(row*128 + seg*16), g_Ef + (size_t)(n0 + row)*256 + kc + seg*8);
            }
            CP_COMMIT();
            CP_WAIT(1);
        } else {
            CP_WAIT(0);
        }
        __syncthreads();

        uint32_t st = base + (c&1)*GB_STG;
        int nst = (c == 3) ? 1 : 4;   // k >= 208 is zero padding
        int rl = lane & 15;
        for (int ks = 0; ks < nst; ks++) {
            int ch = 2*ks + (lane >> 4);
            uint32_t a[4][4];
#pragma unroll
            for (int mi = 0; mi < 4; mi++) {
                int row = wb*64 + mi*16 + rl;
                ldsm_x4(a[mi][0], a[mi][1], a[mi][2], a[mi][3], st + SWZ128(row*128 + ch*16));
            }
            uint32_t bf[4][2];
#pragma unroll
            for (int nj = 0; nj < 2; nj++) {
                uint32_t r0, r1, r2, r3;
                int row = wn*32 + nj*16 + rl;
                ldsm_x4(r0, r1, r2, r3, st + 32768 + SWZ128(row*128 + ch*16));
                bf[nj*2+0][0] = r0; bf[nj*2+0][1] = r2;
                bf[nj*2+1][0] = r1; bf[nj*2+1][1] = r3;
            }
#pragma unroll
            for (int mi = 0; mi < 4; mi++)
#pragma unroll
                for (int ni = 0; ni < 4; ni++)
                    mma16816(acc[mi][ni], a[mi], bf[ni][0], bf[ni][1]);
        }
        __syncthreads();
    }

    // epilogue
    int g = lane >> 2, c2 = (lane & 3)*2;
#pragma unroll
    for (int mi = 0; mi < 4; mi++) {
#pragma unroll
        for (int ni = 0; ni < 4; ni++) {
            int col = n0 + wn*32 + ni*8 + c2;
            if (col < NENT) {
                size_t r0 = (size_t)(b0 + wb*64 + mi*16 + g) * NENT + col;
                size_t r1 = r0 + (size_t)8 * NENT;
                *(float2*)(out + r0) = make_float2(acc[mi][ni][0], acc[mi][ni][1]);
                *(float2*)(out + r1) = make_float2(acc[mi][ni][2], acc[mi][ni][3]);
            }
        }
    }
}

// ---------------- launch ----------------
extern "C" void kernel_launch(void* const* d_in, const int* in_sizes, int n_in,
                              void* d_out, int out_size)
{
    const int*   x   = (const int*)d_in[0];
    const float* E   = (const float*)d_in[1];
    const float* R   = (const float*)d_in[2];
    const float* RnT = (const float*)d_in[3];
    const float* T   = (const float*)d_in[4];
    const float* W   = (const float*)d_in[5];
    const float* g0  = (const float*)d_in[6];
    const float* be0 = (const float*)d_in[7];
    const float* g1  = (const float*)d_in[8];
    const float* be1 = (const float*)d_in[9];
    float* out = (float*)d_out;

    cudaFuncSetAttribute(k_splitW,    cudaFuncAttributeMaxDynamicSharedMemorySize, SPLITW_SMEM);
    cudaFuncSetAttribute(k_gemmA_mma, cudaFuncAttributeMaxDynamicSharedMemorySize, SMEM_GA);
    cudaFuncSetAttribute(k_gemmB_mma, cudaFuncAttributeMaxDynamicSharedMemorySize, SMEM_GB);

    k_gather<<<128, 256>>>(x, E, R, RnT, T);
    k_stats0<<<1, 256>>>(g0, be0);
    k_norm4<<<512, 256>>>(W);
    k_finreg<<<1, 256>>>(out);
    k_splitE<<<NENTP, 128>>>(E);
    k_splitW<<<625, 256, SPLITW_SMEM>>>(W);
    k_prepA<<<BB, 256>>>();
    k_gemmA_mma<<<dim3(16, NSPLIT), 512, SMEM_GA>>>();
    k_redhA<<<1600, 256>>>();
    k_stats1<<<200, 256>>>(g1, be1);
    k_hconv<<<BB, 128>>>();
    k_gemmB_mma<<<dim3(8, 782), 512, SMEM_GB>>>(out);
    cudaMemcpyAsync(out + OFF_T, T, 80000 * sizeof(float), cudaMemcpyDeviceToDevice);
}

// round 8
// speedup vs baseline: 5.4850x; 1.1385x over previous
#include <cuda_runtime.h>
#include <cuda_fp16.h>
#include <cstdint>

typedef unsigned long long ull;

#define BB    2048
#define DIMD  200
#define NENT  100000
#define NENTP 100096
#define WELEM 8000000
#define KKD   40000
#define BNEPS 1e-5f

#define OFF_PRED 0LL
#define OFF_REG  204800000LL
#define OFF_T    204800005LL

#define NSPLIT 25

// ---------------- device scratch ----------------
__device__ float g_lhs  [BB*DIMD];
__device__ float g_relt [BB*DIMD];
__device__ float g_lhsn [BB*DIMD];
__device__ float g_colp [128*2*DIMD];
__device__ float g_s4p  [128*3];
__device__ float g_scale0[DIMD];
__device__ float g_shift0[DIMD];
__device__ float g_regsums[4];
__device__ float g_n4p  [512*2];
__device__ float g_h    [BB*DIMD];
__device__ float g_scale1[DIMD];
__device__ float g_shift1[DIMD];
// fp16 operands
__device__ __half g_Ef [(size_t)NENTP*256];   // E single fp16
__device__ __half g_hf [BB*256];              // h_n single fp16
__device__ __half g_Af [(size_t)BB*KKD];      // A' single fp16
__device__ __half g_Wt [(size_t)256*KKD];     // W^T single fp16
__device__ float g_hpA[(size_t)NSPLIT*BB*256];

// ---------------- helpers ----------------
__device__ __forceinline__ uint32_t smem_u32(const void* p) {
    uint32_t a;
    asm("{ .reg .u64 t; cvta.to.shared.u64 t, %1; cvt.u32.u64 %0, t; }" : "=r"(a) : "l"(p));
    return a;
}
__device__ __forceinline__ void cp16(uint32_t dst, const void* src) {
    asm volatile("cp.async.cg.shared.global [%0], [%1], 16;" :: "r"(dst), "l"(src));
}
#define CP_COMMIT() asm volatile("cp.async.commit_group;" ::: "memory")
#define CP_WAIT(n)  asm volatile("cp.async.wait_group %0;" :: "n"(n) : "memory")

__device__ __forceinline__ void ldsm_x4(uint32_t& r0, uint32_t& r1, uint32_t& r2, uint32_t& r3, uint32_t addr) {
    asm volatile("ldmatrix.sync.aligned.m8n8.x4.shared.b16 {%0,%1,%2,%3}, [%4];"
        : "=r"(r0), "=r"(r1), "=r"(r2), "=r"(r3) : "r"(addr));
}
__device__ __forceinline__ void mma16816(float* c, const uint32_t* a, uint32_t b0, uint32_t b1) {
    asm volatile("mma.sync.aligned.m16n8k16.row.col.f32.f16.f16.f32 "
        "{%0,%1,%2,%3}, {%4,%5,%6,%7}, {%8,%9}, {%0,%1,%2,%3};"
        : "+f"(c[0]), "+f"(c[1]), "+f"(c[2]), "+f"(c[3])
        : "r"(a[0]), "r"(a[1]), "r"(a[2]), "r"(a[3]), "r"(b0), "r"(b1));
}
#define SWZ128(x) ((x) ^ (((x) >> 3) & 0x70))

__device__ __forceinline__ float blockReduce256(float v, float* red) {
    int t = threadIdx.x;
    red[t] = v; __syncthreads();
#pragma unroll
    for (int s = 128; s > 0; s >>= 1) {
        if (t < s) red[t] += red[t + s];
        __syncthreads();
    }
    float r = red[0]; __syncthreads();
    return r;
}

// ---------------- K1: gather + BN0 partials + norm4 partials ----------------
__global__ void k_gather(const int* __restrict__ x,
                         const float* __restrict__ E,
                         const float* __restrict__ R,
                         const float* __restrict__ RnT,
                         const float* __restrict__ T)
{
    __shared__ float red[256];
    int t = threadIdx.x;
    int d = t;
    float cs = 0.f, cq = 0.f, s_rt = 0.f, s_rn = 0.f, s_rh = 0.f;
    if (d < DIMD) {
#pragma unroll 4
        for (int i = 0; i < 16; i++) {
            int b = blockIdx.x * 16 + i;
            int i0 = x[b*4+0], i1 = x[b*4+1], i2 = x[b*4+2], i3 = x[b*4+3];
            float l  = E[(size_t)i0*DIMD + d];
            float rt = R[(size_t)i1*DIMD + d] * T[(size_t)i3*DIMD + d];
            float rn = RnT[(size_t)i1*DIMD + d];
            float rh = E[(size_t)i2*DIMD + d];
            g_lhs [b*DIMD + d] = l;
            g_relt[b*DIMD + d] = rt;
            cs += l; cq += l*l;
            float a = rt*rt;  s_rt += a*a;
            float bq = rn*rn; s_rn += bq*bq;
            float cc = rh*rh; s_rh += cc*cc;
        }
        g_colp[blockIdx.x*2*DIMD + d]        = cs;
        g_colp[blockIdx.x*2*DIMD + DIMD + d] = cq;
    }
    float r0 = blockReduce256(s_rt, red);
    float r1 = blockReduce256(s_rn, red);
    float r2 = blockReduce256(s_rh, red);
    if (t == 0) {
        g_s4p[blockIdx.x*3 + 0] = r0;
        g_s4p[blockIdx.x*3 + 1] = r1;
        g_s4p[blockIdx.x*3 + 2] = r2;
    }
}

// ---------------- K2: BN0 stats + reg sums ----------------
__global__ void k_stats0(const float* __restrict__ gamma0, const float* __restrict__ beta0)
{
    int t = threadIdx.x;
    if (t < DIMD) {
        float s = 0.f, sq = 0.f;
        for (int k = 0; k < 128; k++) {
            s  += g_colp[k*2*DIMD + t];
            sq += g_colp[k*2*DIMD + DIMD + t];
        }
        float mu  = s  * (1.f/2048.f);
        float var = sq * (1.f/2048.f) - mu*mu;
        float rs  = rsqrtf(var + BNEPS);
        float sc  = rs * gamma0[t];
        g_scale0[t] = sc;
        g_shift0[t] = beta0[t] - mu*sc;
    } else if (t < DIMD + 3) {
        int j = t - DIMD;
        float s = 0.f;
        for (int k = 0; k < 128; k++) s += g_s4p[k*3 + j];
        g_regsums[j + 1] = s;
    }
}

// ---------------- K3: norm4(W) + norm4(lhs_n), materialize lhs_n ----------------
__global__ void k_norm4(const float* __restrict__ W)
{
    __shared__ float red[256];
    int t = threadIdx.x;
    float pw = 0.f, pl = 0.f;
    const int TOT = WELEM + BB*DIMD;
    for (int idx = blockIdx.x*256 + t; idx < TOT; idx += 512*256) {
        if (idx < WELEM) {
            float v = W[idx]; float v2 = v*v; pw += v2*v2;
        } else {
            int i = idx - WELEM;
            int d = i % DIMD;
            float v = g_lhs[i] * g_scale0[d] + g_shift0[d];
            g_lhsn[i] = v;
            float v2 = v*v; pl += v2*v2;
        }
    }
    float rl = blockReduce256(pl, red);
    float rw = blockReduce256(pw, red);
    if (t == 0) {
        g_n4p[blockIdx.x*2 + 0] = rl;
        g_n4p[blockIdx.x*2 + 1] = rw;
    }
}

// ---------------- K4: write reg[5] ----------------
__global__ void k_finreg(float* __restrict__ out)
{
    __shared__ float red[256];
    int t = threadIdx.x;
    float a = 0.f, b = 0.f;
    for (int i = t; i < 512; i += 256) { a += g_n4p[2*i]; b += g_n4p[2*i + 1]; }
    float sl = blockReduce256(a, red);
    float sw = blockReduce256(b, red);
    if (t == 0) {
        out[OFF_REG + 0] = powf(sl,           0.25f);
        out[OFF_REG + 1] = powf(g_regsums[1], 0.25f);
        out[OFF_REG + 2] = powf(g_regsums[2], 0.25f);
        out[OFF_REG + 3] = powf(g_regsums[3], 0.25f);
        out[OFF_REG + 4] = powf(sw,           0.25f);
    }
}

// ---------------- K5a: build A' = relt (x) lhsn, single fp16 ----------------
__global__ void k_prepA()
{
    __shared__ float sr[DIMD], sl[DIMD];
    int b = blockIdx.x, t = threadIdx.x;
    if (t < DIMD) { sr[t] = g_relt[b*DIMD + t]; sl[t] = g_lhsn[b*DIMD + t]; }
    __syncthreads();
    size_t rowo = (size_t)b * KKD;
    for (int i2 = 2*t; i2 < KKD; i2 += 512) {
        int k = i2 / DIMD, d = i2 - k*DIMD;   // DIMD even -> pair never straddles k
        float a0 = sr[k]*sl[d];
        float a1 = sr[k]*sl[d+1];
        *(__half2*)&g_Af[rowo + i2] = __floats2half2_rn(a0, a1);
    }
}

// ---------------- K5b: W -> Wt (transposed, single fp16, e padded to 256) ----------------
#define SPLITW_SMEM (64*DIMD*4)
__global__ void k_splitW(const float* __restrict__ W)
{
    extern __shared__ char swraw[];
    float* sm = (float*)swraw;      // 64 x 200
    int t = threadIdx.x;
    int kd0 = blockIdx.x * 64;
    for (int i = t; i < 64*DIMD; i += 256)
        sm[i] = W[(size_t)kd0*DIMD + i];
    __syncthreads();
    for (int idx = t; idx < 256*64; idx += 256) {
        int e = idx >> 6, kd = idx & 63;
        float v = (e < DIMD) ? sm[kd*DIMD + e] : 0.f;
        g_Wt[(size_t)e*KKD + kd0 + kd] = __float2half_rn(v);
    }
}

// ---------------- K5c: GEMM-A via mma.sync fp16, single pass ----------------
// CTA: 128 b x 256 n(e, padded), K-slice 1600 (25 chunks of 64), 512 thr.
// 16 warps = 4b x 4n; warp 32b x 64n. A @0 (16KB), W @16384 (32KB).
#define GA_STG 49152
#define SMEM_GA (2*GA_STG + 1024)
__global__ void __launch_bounds__(512, 1) k_gemmA_mma()
{
    extern __shared__ char smrawA[];
    uint32_t base = (smem_u32(smrawA) + 1023) & ~1023u;

    int t = threadIdx.x;
    int lane = t & 31, wid = t >> 5;
    int wb = wid >> 2, wn = wid & 3;
    int b0  = blockIdx.x * 128;
    int kd0 = blockIdx.y * 1600;

    float acc[2][8][4];
#pragma unroll
    for (int i = 0; i < 2; i++)
#pragma unroll
        for (int j = 0; j < 8; j++)
#pragma unroll
            for (int q = 0; q < 4; q++) acc[i][j][q] = 0.f;

    // prefetch chunk 0
    {
        uint32_t st = base;
#pragma unroll
        for (int j = 0; j < 2; j++) {
            int idx = t + 512*j;
            int row = idx >> 3, seg = idx & 7;
            cp16(st + SWZ128(row*128 + seg*16), g_Af + (size_t)(b0 + row)*KKD + kd0 + seg*8);
        }
#pragma unroll
        for (int j = 0; j < 4; j++) {
            int idx = t + 512*j;
            int row = idx >> 3, seg = idx & 7;
            cp16(st + 16384 + SWZ128(row*128 + seg*16), g_Wt + (size_t)row*KKD + kd0 + seg*8);
        }
        CP_COMMIT();
    }

    for (int c = 0; c < 25; c++) {
        if (c + 1 < 25) {
            int kc = (c+1)*64;
            uint32_t st = base + ((c+1)&1)*GA_STG;
#pragma unroll
            for (int j = 0; j < 2; j++) {
                int idx = t + 512*j;
                int row = idx >> 3, seg = idx & 7;
                cp16(st + SWZ128(row*128 + seg*16), g_Af + (size_t)(b0 + row)*KKD + kd0 + kc + seg*8);
            }
#pragma unroll
            for (int j = 0; j < 4; j++) {
                int idx = t + 512*j;
                int row = idx >> 3, seg = idx & 7;
                cp16(st + 16384 + SWZ128(row*128 + seg*16), g_Wt + (size_t)row*KKD + kd0 + kc + seg*8);
            }
            CP_COMMIT();
            CP_WAIT(1);
        } else {
            CP_WAIT(0);
        }
        __syncthreads();

        uint32_t st = base + (c&1)*GA_STG;
        int rl = lane & 15;
        for (int ks = 0; ks < 4; ks++) {
            int ch = 2*ks + (lane >> 4);
            uint32_t a[2][4];
#pragma unroll
            for (int mi = 0; mi < 2; mi++) {
                int row = wb*32 + mi*16 + rl;
                ldsm_x4(a[mi][0], a[mi][1], a[mi][2], a[mi][3], st + SWZ128(row*128 + ch*16));
            }
            uint32_t bf[8][2];
#pragma unroll
            for (int nj = 0; nj < 4; nj++) {
                uint32_t r0, r1, r2, r3;
                int row = wn*64 + nj*16 + rl;
                ldsm_x4(r0, r1, r2, r3, st + 16384 + SWZ128(row*128 + ch*16));
                bf[nj*2+0][0] = r0; bf[nj*2+0][1] = r2;
                bf[nj*2+1][0] = r1; bf[nj*2+1][1] = r3;
            }
#pragma unroll
            for (int mi = 0; mi < 2; mi++)
#pragma unroll
                for (int ni = 0; ni < 8; ni++)
                    mma16816(acc[mi][ni], a[mi], bf[ni][0], bf[ni][1]);
        }
        __syncthreads();
    }

    float* dst = g_hpA + (size_t)blockIdx.y * (BB*256);
    int g = lane >> 2, c2 = (lane & 3)*2;
#pragma unroll
    for (int mi = 0; mi < 2; mi++) {
#pragma unroll
        for (int ni = 0; ni < 8; ni++) {
            int col = wn*64 + ni*8 + c2;
            if (col < DIMD) {
                size_t r0 = (size_t)(b0 + wb*32 + mi*16 + g) * 256 + col;
                *(float2*)(dst + r0)         = make_float2(acc[mi][ni][0], acc[mi][ni][1]);
                *(float2*)(dst + r0 + 8*256) = make_float2(acc[mi][ni][2], acc[mi][ni][3]);
            }
        }
    }
}

// ---------------- K6: reduce k-split partials ----------------
__global__ void k_redhA()
{
    int i = blockIdx.x*256 + threadIdx.x;
    if (i < BB*DIMD) {
        int b = i / DIMD, n = i - b*DIMD;
        float s = 0.f;
#pragma unroll
        for (int ks = 0; ks < NSPLIT; ks++)
            s += g_hpA[(size_t)ks*(BB*256) + (size_t)b*256 + n];
        g_h[i] = s;
    }
}

// ---------------- K7: BN1 stats ----------------
__global__ void k_stats1(const float* __restrict__ gamma1, const float* __restrict__ beta1)
{
    __shared__ float r0[256];
    int e = blockIdx.x, t = threadIdx.x;
    float s = 0.f, sq = 0.f;
    for (int b = t; b < BB; b += 256) {
        float v = g_h[b*DIMD + e];
        s += v; sq += v*v;
    }
    float ts = blockReduce256(s, r0);
    float tq = blockReduce256(sq, r0);
    if (t == 0) {
        float mu  = ts * (1.f/2048.f);
        float var = tq * (1.f/2048.f) - mu*mu;
        float rs  = rsqrtf(var + BNEPS);
        float sc  = rs * gamma1[e];
        g_scale1[e] = sc;
        g_shift1[e] = beta1[e] - mu*sc;
    }
}

// ---------------- K8a: E -> fp16 single (padded) ----------------
__global__ void k_splitE(const float* __restrict__ E)
{
    int r = blockIdx.x;
    int c = threadIdx.x * 2;
    float v0 = 0.f, v1 = 0.f;
    if (r < NENT) {
        if (c < DIMD)     v0 = E[(size_t)r*DIMD + c];
        if (c + 1 < DIMD) v1 = E[(size_t)r*DIMD + c + 1];
    }
    *(__half2*)&g_Ef[(size_t)r*256 + c] = __floats2half2_rn(v0, v1);
}

// ---------------- K8b: BN1 apply, h_n -> single fp16 ----------------
__global__ void k_hconv()
{
    int b = blockIdx.x;
    int c = threadIdx.x * 2;
    float v0 = 0.f, v1 = 0.f;
    if (c < DIMD)     v0 = g_h[b*DIMD + c]     * g_scale1[c]     + g_shift1[c];
    if (c + 1 < DIMD) v1 = g_h[b*DIMD + c + 1] * g_scale1[c + 1] + g_shift1[c + 1];
    *(__half2*)&g_hf[(size_t)b*256 + c] = __floats2half2_rn(v0, v1);
}

// ---------------- K9: GEMM-B via mma.sync fp16, single pass ----------------
// CTA: 256 b x 128 n, 512 thr. 16 warps = 4b x 4n; warp 64b x 32n.
// 4 K-chunks of 64. h @0 (32KB), E @32768 (16KB). b fastest in grid -> E L2 reuse.
#define GB_STG 49152
#define SMEM_GB (2*GB_STG + 1024)
__global__ void __launch_bounds__(512, 1) k_gemmB_mma(float* __restrict__ out)
{
    extern __shared__ char smrawB[];
    uint32_t base = (smem_u32(smrawB) + 1023) & ~1023u;

    int t = threadIdx.x;
    int lane = t & 31, wid = t >> 5;
    int wb = wid >> 2, wn = wid & 3;
    int b0 = blockIdx.x * 256;   // 8 values, fastest -> concurrent CTAs share E tile
    int n0 = blockIdx.y * 128;

    float acc[4][4][4];
#pragma unroll
    for (int i = 0; i < 4; i++)
#pragma unroll
        for (int j = 0; j < 4; j++)
#pragma unroll
            for (int q = 0; q < 4; q++) acc[i][j][q] = 0.f;

    // prefetch chunk 0
    {
        uint32_t st = base;
#pragma unroll
        for (int j = 0; j < 4; j++) {
            int idx = t + 512*j;
            int row = idx >> 3, seg = idx & 7;
            cp16(st + SWZ128(row*128 + seg*16), g_hf + (size_t)(b0 + row)*256 + seg*8);
        }
#pragma unroll
        for (int j = 0; j < 2; j++) {
            int idx = t + 512*j;
            int row = idx >> 3, seg = idx & 7;
            cp16(st + 32768 + SWZ128(row*128 + seg*16), g_Ef + (size_t)(n0 + row)*256 + seg*8);
        }
        CP_COMMIT();
    }

    for (int c = 0; c < 4; c++) {
        if (c + 1 < 4) {
            int kc = (c+1)*64;
            uint32_t st = base + ((c+1)&1)*GB_STG;
#pragma unroll
            for (int j = 0; j < 4; j++) {
                int idx = t + 512*j;
                int row = idx >> 3, seg = idx & 7;
                cp16(st + SWZ128(row*128 + seg*16), g_hf + (size_t)(b0 + row)*256 + kc + seg*8);
            }
#pragma unroll
            for (int j = 0; j < 2; j++) {
                int idx = t + 512*j;
                int row = idx >> 3, seg = idx & 7;
                cp16(st + 32768 + SWZ128(row*128 + seg*16), g_Ef + (size_t)(n0 + row)*256 + kc + seg*8);
            }
            CP_COMMIT();
            CP_WAIT(1);
        } else {
            CP_WAIT(0);
        }
        __syncthreads();

        uint32_t st = base + (c&1)*GB_STG;
        int nst = (c == 3) ? 1 : 4;   // k >= 208 is zero padding
        int rl = lane & 15;
        for (int ks = 0; ks < nst; ks++) {
            int ch = 2*ks + (lane >> 4);
            uint32_t a[4][4];
#pragma unroll
            for (int mi = 0; mi < 4; mi++) {
                int row = wb*64 + mi*16 + rl;
                ldsm_x4(a[mi][0], a[mi][1], a[mi][2], a[mi][3], st + SWZ128(row*128 + ch*16));
            }
            uint32_t bf[4][2];
#pragma unroll
            for (int nj = 0; nj < 2; nj++) {
                uint32_t r0, r1, r2, r3;
                int row = wn*32 + nj*16 + rl;
                ldsm_x4(r0, r1, r2, r3, st + 32768 + SWZ128(row*128 + ch*16));
                bf[nj*2+0][0] = r0; bf[nj*2+0][1] = r2;
                bf[nj*2+1][0] = r1; bf[nj*2+1][1] = r3;
            }
#pragma unroll
            for (int mi = 0; mi < 4; mi++)
#pragma unroll
                for (int ni = 0; ni < 4; ni++)
                    mma16816(acc[mi][ni], a[mi], bf[ni][0], bf[ni][1]);
        }
        __syncthreads();
    }

    // epilogue
    int g = lane >> 2, c2 = (lane & 3)*2;
#pragma unroll
    for (int mi = 0; mi < 4; mi++) {
#pragma unroll
        for (int ni = 0; ni < 4; ni++) {
            int col = n0 + wn*32 + ni*8 + c2;
            if (col < NENT) {
                size_t r0 = (size_t)(b0 + wb*64 + mi*16 + g) * NENT + col;
                size_t r1 = r0 + (size_t)8 * NENT;
                *(float2*)(out + r0) = make_float2(acc[mi][ni][0], acc[mi][ni][1]);
                *(float2*)(out + r1) = make_float2(acc[mi][ni][2], acc[mi][ni][3]);
            }
        }
    }
}

// ---------------- launch ----------------
extern "C" void kernel_launch(void* const* d_in, const int* in_sizes, int n_in,
                              void* d_out, int out_size)
{
    const int*   x   = (const int*)d_in[0];
    const float* E   = (const float*)d_in[1];
    const float* R   = (const float*)d_in[2];
    const float* RnT = (const float*)d_in[3];
    const float* T   = (const float*)d_in[4];
    const float* W   = (const float*)d_in[5];
    const float* g0  = (const float*)d_in[6];
    const float* be0 = (const float*)d_in[7];
    const float* g1  = (const float*)d_in[8];
    const float* be1 = (const float*)d_in[9];
    float* out = (float*)d_out;

    cudaFuncSetAttribute(k_splitW,    cudaFuncAttributeMaxDynamicSharedMemorySize, SPLITW_SMEM);
    cudaFuncSetAttribute(k_gemmA_mma, cudaFuncAttributeMaxDynamicSharedMemorySize, SMEM_GA);
    cudaFuncSetAttribute(k_gemmB_mma, cudaFuncAttributeMaxDynamicSharedMemorySize, SMEM_GB);

    k_gather<<<128, 256>>>(x, E, R, RnT, T);
    k_stats0<<<1, 256>>>(g0, be0);
    k_norm4<<<512, 256>>>(W);
    k_finreg<<<1, 256>>>(out);
    k_splitE<<<NENTP, 128>>>(E);
    k_splitW<<<625, 256, SPLITW_SMEM>>>(W);
    k_prepA<<<BB, 256>>>();
    k_gemmA_mma<<<dim3(16, NSPLIT), 512, SMEM_GA>>>();
    k_redhA<<<1600, 256>>>();
    k_stats1<<<200, 256>>>(g1, be1);
    k_hconv<<<BB, 128>>>();
    k_gemmB_mma<<<dim3(8, 782), 512, SMEM_GB>>>(out);
    cudaMemcpyAsync(out + OFF_T, T, 80000 * sizeof(float), cudaMemcpyDeviceToDevice);
}